// round 3
// baseline (speedup 1.0000x reference)
#include <cuda_runtime.h>
#include <cuda_bf16.h>
#include <cstdint>

#define D_MODELX 1024
#define NUM_HEADSX 16
#define D_HEADX 64
#define BATCHX 4
#define SEQX 2048
#define M_TOK (BATCHX * SEQX)   // 8192
#define NZ (BATCHX * NUM_HEADSX) // 64

// ---- static device scratch ----
__device__ __nv_bfloat16 g_xh[(size_t)M_TOK * D_MODELX];
__device__ __nv_bfloat16 g_xl[(size_t)M_TOK * D_MODELX];
__device__ __nv_bfloat16 g_wh[(size_t)D_MODELX * D_MODELX];
__device__ __nv_bfloat16 g_wl[(size_t)D_MODELX * D_MODELX];
__device__ __nv_bfloat16 g_Qh[(size_t)M_TOK * D_MODELX];
__device__ __nv_bfloat16 g_Ql[(size_t)M_TOK * D_MODELX];
__device__ __nv_bfloat16 g_Kh[(size_t)M_TOK * D_MODELX];
__device__ __nv_bfloat16 g_Kl[(size_t)M_TOK * D_MODELX];
__device__ __nv_bfloat16 g_Vth[(size_t)M_TOK * D_MODELX];  // [Z][64][2048]
__device__ __nv_bfloat16 g_Vtl[(size_t)M_TOK * D_MODELX];
__device__ __nv_bfloat16 g_Oh[(size_t)M_TOK * D_MODELX];
__device__ __nv_bfloat16 g_Ol[(size_t)M_TOK * D_MODELX];
__device__ float g_P[(size_t)NZ * SEQX * SEQX];             // 1 GiB raw scores
__device__ float g_rmax[(size_t)NZ * SEQX];
__device__ float g_rinv[(size_t)NZ * SEQX];

__device__ __forceinline__ unsigned pack_bf2(float x, float y) {
    __nv_bfloat162 t = __floats2bfloat162_rn(x, y);
    return *reinterpret_cast<unsigned*>(&t);
}

#define MMA_BF16(c, a0, a1, a2, a3, b0, b1)                                   \
    asm volatile(                                                             \
        "mma.sync.aligned.m16n8k16.row.col.f32.bf16.bf16.f32 "                \
        "{%0,%1,%2,%3},{%4,%5,%6,%7},{%8,%9},{%0,%1,%2,%3};"                  \
        : "+f"(c[0]), "+f"(c[1]), "+f"(c[2]), "+f"(c[3])                      \
        : "r"(a0), "r"(a1), "r"(a2), "r"(a3), "r"(b0), "r"(b1))

// ============================================================================
// split: fp32 -> bf16 hi + bf16 lo
// ============================================================================
__global__ __launch_bounds__(256)
void split_kernel(const float4* __restrict__ src,
                  __nv_bfloat16* __restrict__ dh,
                  __nv_bfloat16* __restrict__ dl, int n4)
{
    int i = blockIdx.x * 256 + threadIdx.x;
    if (i >= n4) return;
    float4 v = src[i];
    float h0 = __bfloat162float(__float2bfloat16_rn(v.x));
    float h1 = __bfloat162float(__float2bfloat16_rn(v.y));
    float h2 = __bfloat162float(__float2bfloat16_rn(v.z));
    float h3 = __bfloat162float(__float2bfloat16_rn(v.w));
    uint2 H, L;
    H.x = pack_bf2(v.x, v.y); H.y = pack_bf2(v.z, v.w);
    L.x = pack_bf2(v.x - h0, v.y - h1); L.y = pack_bf2(v.z - h2, v.w - h3);
    *(uint2*)&dh[(size_t)i * 4] = H;
    *(uint2*)&dl[(size_t)i * 4] = L;
}

// ============================================================================
// Pre-split bf16 NT GEMM: C = alpha * (A @ B^T) + bias, 3-pass bf16 split MMA.
// Block tile 128x64x64, 256 threads (8 warps 4x2), warp tile 32x32.
// MODE 0 OUT_BF : C -> Ch/Cl bf16 pair, + bias
// MODE 1 VT     : V projection, transposed bf16 store into [Z][64][2048]
// MODE 2 SCORES : per-z head slices; C -> fp32 P, alpha
// MODE 3 AV     : A = raw P fp32 with exp(x-m)*inv on load; B = Vt; C -> Oh/Ol
// MODE 4 OUT_F32: C -> fp32 + bias (final output)
// ============================================================================
template <int MODE>
__global__ __launch_bounds__(256)
void gemm2(const __nv_bfloat16* __restrict__ Ah, const __nv_bfloat16* __restrict__ Al,
           const float* __restrict__ Af,
           const __nv_bfloat16* __restrict__ Bh, const __nv_bfloat16* __restrict__ Bl,
           float* __restrict__ Cf,
           __nv_bfloat16* __restrict__ Ch, __nv_bfloat16* __restrict__ Cl,
           int lda, int ldb, int ldc, int K, float alpha,
           const float* __restrict__ bias,
           const float* __restrict__ rmax, const float* __restrict__ rinv)
{
    constexpr int BM = 128, BN = 64, BK = 64;
    constexpr int SA = 72;  // bf16 stride: conflict-free frag loads, 16B-aligned rows

    __shared__ __align__(16) __nv_bfloat16 AsH[BM * SA];
    __shared__ __align__(16) __nv_bfloat16 AsL[BM * SA];
    __shared__ __align__(16) __nv_bfloat16 BsH[BN * SA];
    __shared__ __align__(16) __nv_bfloat16 BsL[BN * SA];
    __shared__ float sm_m[BM], sm_i[BM];

    int zb = 0, zh = 0;
    if (MODE == 2 || MODE == 3) {
        int z = blockIdx.z; zb = z >> 4; zh = z & 15;
        if (MODE == 2) {
            size_t ao = (size_t)zb * SEQX * D_MODELX + zh * D_HEADX;
            Ah += ao; Al += ao; Bh += ao; Bl += ao;
            Cf += (size_t)z * SEQX * SEQX;
        } else {
            Af += (size_t)z * SEQX * SEQX;
            size_t bo = (size_t)z * D_HEADX * SEQX;
            Bh += bo; Bl += bo;
            size_t co = (size_t)zb * SEQX * D_MODELX + zh * D_HEADX;
            Ch += co; Cl += co;
            rmax += (size_t)z * SEQX; rinv += (size_t)z * SEQX;
        }
    }

    const int tid  = threadIdx.x;
    const int m0   = blockIdx.y * BM;
    const int n0   = blockIdx.x * BN;
    const int warp = tid >> 5, lane = tid & 31;
    const int wm = (warp & 3) * 32;
    const int wn = (warp >> 2) * 32;
    const int gr = lane >> 2;
    const int gc = lane & 3;

    if (MODE == 3) {
        if (tid < BM) { sm_m[tid] = rmax[m0 + tid]; sm_i[tid] = rinv[m0 + tid]; }
        __syncthreads();
    }

    float acc[2][4][4] = {};

    // ---- register prefetch buffers ----
    uint4  pah[4], pal[4];   // bf16 A modes: 4 x 8 bf16 per array
    float4 paf[8];           // AV mode: fp32 A
    uint4  pbh[2], pbl[2];

    // prefetch tile 0
    {
        if (MODE == 3) {
            #pragma unroll
            for (int i = 0; i < 8; i++) {
                int idx = tid + i * 256, row = idx >> 4, c4 = idx & 15;
                paf[i] = *(const float4*)(Af + (size_t)(m0 + row) * lda + c4 * 4);
            }
        } else {
            #pragma unroll
            for (int i = 0; i < 4; i++) {
                int idx = tid + i * 256, row = idx >> 3, c8 = idx & 7;
                size_t off = (size_t)(m0 + row) * lda + c8 * 8;
                pah[i] = *(const uint4*)(Ah + off);
                pal[i] = *(const uint4*)(Al + off);
            }
        }
        #pragma unroll
        for (int i = 0; i < 2; i++) {
            int idx = tid + i * 256, row = idx >> 3, c8 = idx & 7;
            size_t off = (size_t)(n0 + row) * ldb + c8 * 8;
            pbh[i] = *(const uint4*)(Bh + off);
            pbl[i] = *(const uint4*)(Bl + off);
        }
    }

    const int niter = K / BK;
    for (int it = 0; it < niter; ++it) {
        // ---- regs -> smem ----
        if (MODE == 3) {
            #pragma unroll
            for (int i = 0; i < 8; i++) {
                int idx = tid + i * 256, row = idx >> 4, c4 = idx & 15;
                float m = sm_m[row], inv = sm_i[row];
                float e0 = __expf(paf[i].x - m) * inv;
                float e1 = __expf(paf[i].y - m) * inv;
                float e2 = __expf(paf[i].z - m) * inv;
                float e3 = __expf(paf[i].w - m) * inv;
                float h0 = __bfloat162float(__float2bfloat16_rn(e0));
                float h1 = __bfloat162float(__float2bfloat16_rn(e1));
                float h2 = __bfloat162float(__float2bfloat16_rn(e2));
                float h3 = __bfloat162float(__float2bfloat16_rn(e3));
                uint2 H, L;
                H.x = pack_bf2(e0, e1); H.y = pack_bf2(e2, e3);
                L.x = pack_bf2(e0 - h0, e1 - h1); L.y = pack_bf2(e2 - h2, e3 - h3);
                *(uint2*)&AsH[row * SA + c4 * 4] = H;
                *(uint2*)&AsL[row * SA + c4 * 4] = L;
            }
        } else {
            #pragma unroll
            for (int i = 0; i < 4; i++) {
                int idx = tid + i * 256, row = idx >> 3, c8 = idx & 7;
                *(uint4*)&AsH[row * SA + c8 * 8] = pah[i];
                *(uint4*)&AsL[row * SA + c8 * 8] = pal[i];
            }
        }
        #pragma unroll
        for (int i = 0; i < 2; i++) {
            int idx = tid + i * 256, row = idx >> 3, c8 = idx & 7;
            *(uint4*)&BsH[row * SA + c8 * 8] = pbh[i];
            *(uint4*)&BsL[row * SA + c8 * 8] = pbl[i];
        }
        __syncthreads();

        // ---- prefetch next ----
        if (it + 1 < niter) {
            int k0 = (it + 1) * BK;
            if (MODE == 3) {
                #pragma unroll
                for (int i = 0; i < 8; i++) {
                    int idx = tid + i * 256, row = idx >> 4, c4 = idx & 15;
                    paf[i] = *(const float4*)(Af + (size_t)(m0 + row) * lda + k0 + c4 * 4);
                }
            } else {
                #pragma unroll
                for (int i = 0; i < 4; i++) {
                    int idx = tid + i * 256, row = idx >> 3, c8 = idx & 7;
                    size_t off = (size_t)(m0 + row) * lda + k0 + c8 * 8;
                    pah[i] = *(const uint4*)(Ah + off);
                    pal[i] = *(const uint4*)(Al + off);
                }
            }
            #pragma unroll
            for (int i = 0; i < 2; i++) {
                int idx = tid + i * 256, row = idx >> 3, c8 = idx & 7;
                size_t off = (size_t)(n0 + row) * ldb + k0 + c8 * 8;
                pbh[i] = *(const uint4*)(Bh + off);
                pbl[i] = *(const uint4*)(Bl + off);
            }
        }

        // ---- compute: 4 k-steps of 16 ----
        #pragma unroll
        for (int ks = 0; ks < 4; ks++) {
            const int kb = ks * 16;
            unsigned aH[2][4], aL[2][4], bH[4][2], bL[4][2];
            #pragma unroll
            for (int mi = 0; mi < 2; mi++) {
                int r = (wm + mi * 16 + gr) * SA + kb + gc * 2;
                aH[mi][0] = *(const unsigned*)&AsH[r];
                aH[mi][1] = *(const unsigned*)&AsH[r + 8 * SA];
                aH[mi][2] = *(const unsigned*)&AsH[r + 8];
                aH[mi][3] = *(const unsigned*)&AsH[r + 8 * SA + 8];
                aL[mi][0] = *(const unsigned*)&AsL[r];
                aL[mi][1] = *(const unsigned*)&AsL[r + 8 * SA];
                aL[mi][2] = *(const unsigned*)&AsL[r + 8];
                aL[mi][3] = *(const unsigned*)&AsL[r + 8 * SA + 8];
            }
            #pragma unroll
            for (int ni = 0; ni < 4; ni++) {
                int r = (wn + ni * 8 + gr) * SA + kb + gc * 2;
                bH[ni][0] = *(const unsigned*)&BsH[r];
                bH[ni][1] = *(const unsigned*)&BsH[r + 8];
                bL[ni][0] = *(const unsigned*)&BsL[r];
                bL[ni][1] = *(const unsigned*)&BsL[r + 8];
            }
            #pragma unroll
            for (int mi = 0; mi < 2; mi++)
                #pragma unroll
                for (int ni = 0; ni < 4; ni++) {
                    MMA_BF16(acc[mi][ni], aH[mi][0], aH[mi][1], aH[mi][2], aH[mi][3],
                             bH[ni][0], bH[ni][1]);
                    MMA_BF16(acc[mi][ni], aH[mi][0], aH[mi][1], aH[mi][2], aH[mi][3],
                             bL[ni][0], bL[ni][1]);
                    MMA_BF16(acc[mi][ni], aL[mi][0], aL[mi][1], aL[mi][2], aL[mi][3],
                             bH[ni][0], bH[ni][1]);
                }
        }
        __syncthreads();
    }

    // ---- epilogue ----
    #pragma unroll
    for (int mi = 0; mi < 2; mi++)
        #pragma unroll
        for (int ni = 0; ni < 4; ni++) {
            int r = m0 + wm + mi * 16 + gr;
            int c = n0 + wn + ni * 8 + gc * 2;
            float* cc = acc[mi][ni];
            if (MODE == 1) {
                // transposed bf16 store into Vt [Z][64][2048]
                int b = r >> 11, s = r & 2047;
                int h = c >> 6, d = c & 63;
                float b0 = bias[c], b1 = bias[c + 1];
                size_t base = ((size_t)(b * 16 + h) * 64 + d) * 2048;
                float v00 = cc[0] + b0, v01 = cc[1] + b1;
                float v10 = cc[2] + b0, v11 = cc[3] + b1;
                Ch[base + s]            = __float2bfloat16_rn(v00);
                Ch[base + 2048 + s]     = __float2bfloat16_rn(v01);
                Ch[base + s + 8]        = __float2bfloat16_rn(v10);
                Ch[base + 2048 + s + 8] = __float2bfloat16_rn(v11);
                Cl[base + s]            = __float2bfloat16_rn(v00 - __bfloat162float(__float2bfloat16_rn(v00)));
                Cl[base + 2048 + s]     = __float2bfloat16_rn(v01 - __bfloat162float(__float2bfloat16_rn(v01)));
                Cl[base + s + 8]        = __float2bfloat16_rn(v10 - __bfloat162float(__float2bfloat16_rn(v10)));
                Cl[base + 2048 + s + 8] = __float2bfloat16_rn(v11 - __bfloat162float(__float2bfloat16_rn(v11)));
            } else if (MODE == 2) {
                float2 v0 = make_float2(cc[0] * alpha, cc[1] * alpha);
                float2 v1 = make_float2(cc[2] * alpha, cc[3] * alpha);
                *(float2*)&Cf[(size_t)r * ldc + c]       = v0;
                *(float2*)&Cf[(size_t)(r + 8) * ldc + c] = v1;
            } else if (MODE == 4) {
                float b0 = bias[c], b1 = bias[c + 1];
                float2 v0 = make_float2(cc[0] + b0, cc[1] + b1);
                float2 v1 = make_float2(cc[2] + b0, cc[3] + b1);
                *(float2*)&Cf[(size_t)r * ldc + c]       = v0;
                *(float2*)&Cf[(size_t)(r + 8) * ldc + c] = v1;
            } else {
                // MODE 0 / MODE 3: bf16 pair out (bias optional)
                float b0 = 0.f, b1 = 0.f;
                if (bias) { b0 = bias[c]; b1 = bias[c + 1]; }
                float v00 = cc[0] + b0, v01 = cc[1] + b1;
                float v10 = cc[2] + b0, v11 = cc[3] + b1;
                float h00 = __bfloat162float(__float2bfloat16_rn(v00));
                float h01 = __bfloat162float(__float2bfloat16_rn(v01));
                float h10 = __bfloat162float(__float2bfloat16_rn(v10));
                float h11 = __bfloat162float(__float2bfloat16_rn(v11));
                size_t o0 = (size_t)r * ldc + c;
                size_t o1 = (size_t)(r + 8) * ldc + c;
                *(unsigned*)&Ch[o0] = pack_bf2(v00, v01);
                *(unsigned*)&Ch[o1] = pack_bf2(v10, v11);
                *(unsigned*)&Cl[o0] = pack_bf2(v00 - h00, v01 - h01);
                *(unsigned*)&Cl[o1] = pack_bf2(v10 - h10, v11 - h11);
            }
        }
}

// ============================================================================
// stats + head-average: per (b,q), for each head compute row max & 1/sumexp
// (stored for the AV kernel), accumulate the head-averaged probabilities.
// P is NOT rewritten.
// ============================================================================
__global__ __launch_bounds__(256)
void stats_avg_kernel(const float* __restrict__ P, float* __restrict__ avg,
                      float* __restrict__ rmax, float* __restrict__ rinv)
{
    __shared__ float red[8];
    const int bq = blockIdx.x;
    const int t  = threadIdx.x;
    const int b  = bq >> 11;
    const int q  = bq & 2047;

    float avgacc[8] = {};

    for (int h = 0; h < NUM_HEADSX; ++h) {
        const int z = b * 16 + h;
        const float* p = P + ((size_t)z * SEQX + q) * SEQX;
        float v[8];
        float mx = -1e30f;
        #pragma unroll
        for (int i = 0; i < 8; i++) { v[i] = p[t + i * 256]; mx = fmaxf(mx, v[i]); }
        #pragma unroll
        for (int o = 16; o > 0; o >>= 1)
            mx = fmaxf(mx, __shfl_xor_sync(0xffffffffu, mx, o));
        if ((t & 31) == 0) red[t >> 5] = mx;
        __syncthreads();
        float bm = red[0];
        #pragma unroll
        for (int w = 1; w < 8; w++) bm = fmaxf(bm, red[w]);
        __syncthreads();

        float s = 0.f;
        #pragma unroll
        for (int i = 0; i < 8; i++) { v[i] = __expf(v[i] - bm); s += v[i]; }
        #pragma unroll
        for (int o = 16; o > 0; o >>= 1)
            s += __shfl_xor_sync(0xffffffffu, s, o);
        if ((t & 31) == 0) red[t >> 5] = s;
        __syncthreads();
        float bs = 0.f;
        #pragma unroll
        for (int w = 0; w < 8; w++) bs += red[w];
        float inv = 1.0f / bs;
        if (t == 0) {
            rmax[(size_t)z * SEQX + q] = bm;
            rinv[(size_t)z * SEQX + q] = inv;
        }
        #pragma unroll
        for (int i = 0; i < 8; i++) avgacc[i] += v[i] * inv;
        __syncthreads();
    }

    float* a = avg + (size_t)bq * SEQX;
    #pragma unroll
    for (int i = 0; i < 8; i++)
        a[t + i * 256] = avgacc[i] * (1.0f / NUM_HEADSX);
}

// ============================================================================
// launch
// ============================================================================
extern "C" void kernel_launch(void* const* d_in, const int* in_sizes, int n_in,
                              void* d_out, int out_size)
{
    const float* x_q = (const float*)d_in[0];
    const float* x_k = (const float*)d_in[1];
    const float* x_v = (const float*)d_in[2];
    const float* Wq  = (const float*)d_in[3];
    const float* bq  = (const float*)d_in[4];
    const float* Wk  = (const float*)d_in[5];
    const float* bk  = (const float*)d_in[6];
    const float* Wv  = (const float*)d_in[7];
    const float* bv  = (const float*)d_in[8];
    const float* Wo  = (const float*)d_in[9];
    const float* bo  = (const float*)d_in[10];

    float* out = (float*)d_out;
    float* avg = out + (size_t)M_TOK * D_MODELX;

    __nv_bfloat16 *xh, *xl, *wh, *wl, *Qh, *Ql, *Kh, *Kl, *Vth, *Vtl, *Oh, *Ol;
    float *P, *rmax, *rinv;
    cudaGetSymbolAddress((void**)&xh, g_xh);  cudaGetSymbolAddress((void**)&xl, g_xl);
    cudaGetSymbolAddress((void**)&wh, g_wh);  cudaGetSymbolAddress((void**)&wl, g_wl);
    cudaGetSymbolAddress((void**)&Qh, g_Qh);  cudaGetSymbolAddress((void**)&Ql, g_Ql);
    cudaGetSymbolAddress((void**)&Kh, g_Kh);  cudaGetSymbolAddress((void**)&Kl, g_Kl);
    cudaGetSymbolAddress((void**)&Vth, g_Vth); cudaGetSymbolAddress((void**)&Vtl, g_Vtl);
    cudaGetSymbolAddress((void**)&Oh, g_Oh);  cudaGetSymbolAddress((void**)&Ol, g_Ol);
    cudaGetSymbolAddress((void**)&P, g_P);
    cudaGetSymbolAddress((void**)&rmax, g_rmax);
    cudaGetSymbolAddress((void**)&rinv, g_rinv);

    dim3 blk(256);
    const int nx4 = M_TOK * D_MODELX / 4;      // 2M
    const int nw4 = D_MODELX * D_MODELX / 4;   // 256K
    dim3 gproj(D_MODELX / 64, M_TOK / 128, 1); // (16, 64)

    // ---- Q projection ----
    split_kernel<<<nx4 / 256, blk>>>((const float4*)x_q, xh, xl, nx4);
    split_kernel<<<nw4 / 256, blk>>>((const float4*)Wq, wh, wl, nw4);
    gemm2<0><<<gproj, blk>>>(xh, xl, nullptr, wh, wl, nullptr, Qh, Ql,
                             D_MODELX, D_MODELX, D_MODELX, D_MODELX, 1.0f, bq,
                             nullptr, nullptr);
    // ---- K projection ----
    split_kernel<<<nx4 / 256, blk>>>((const float4*)x_k, xh, xl, nx4);
    split_kernel<<<nw4 / 256, blk>>>((const float4*)Wk, wh, wl, nw4);
    gemm2<0><<<gproj, blk>>>(xh, xl, nullptr, wh, wl, nullptr, Kh, Kl,
                             D_MODELX, D_MODELX, D_MODELX, D_MODELX, 1.0f, bk,
                             nullptr, nullptr);
    // ---- V projection (transposed out) ----
    split_kernel<<<nx4 / 256, blk>>>((const float4*)x_v, xh, xl, nx4);
    split_kernel<<<nw4 / 256, blk>>>((const float4*)Wv, wh, wl, nw4);
    gemm2<1><<<gproj, blk>>>(xh, xl, nullptr, wh, wl, nullptr, Vth, Vtl,
                             D_MODELX, D_MODELX, 0, D_MODELX, 1.0f, bv,
                             nullptr, nullptr);

    // ---- scores: raw P = (Q_h @ K_h^T) / 8 ----
    dim3 gsc(SEQX / 64, SEQX / 128, NZ);       // (32, 16, 64)
    gemm2<2><<<gsc, blk>>>(Qh, Ql, nullptr, Kh, Kl, P, nullptr, nullptr,
                           D_MODELX, D_MODELX, SEQX, D_HEADX, 0.125f, nullptr,
                           nullptr, nullptr);

    // ---- stats + head-average ----
    stats_avg_kernel<<<M_TOK, blk>>>(P, avg, rmax, rinv);

    // ---- AV: O_h = softmax(P)[z] @ Vt[z]^T (exp applied on the fly) ----
    dim3 gav(1, SEQX / 128, NZ);               // (1, 16, 64)
    gemm2<3><<<gav, blk>>>(nullptr, nullptr, P, Vth, Vtl, nullptr, Oh, Ol,
                           SEQX, SEQX, D_MODELX, SEQX, 1.0f, nullptr,
                           rmax, rinv);

    // ---- output projection ----
    split_kernel<<<nw4 / 256, blk>>>((const float4*)Wo, wh, wl, nw4);
    gemm2<4><<<gproj, blk>>>(Oh, Ol, nullptr, wh, wl, out, nullptr, nullptr,
                             D_MODELX, D_MODELX, D_MODELX, D_MODELX, 1.0f, bo,
                             nullptr, nullptr);
}

// round 4
// speedup vs baseline: 1.1670x; 1.1670x over previous
#include <cuda_runtime.h>
#include <cuda_bf16.h>
#include <cuda_fp16.h>
#include <cstdint>

#define D_MODELX 1024
#define NUM_HEADSX 16
#define D_HEADX 64
#define BATCHX 4
#define SEQX 2048
#define M_TOK (BATCHX * SEQX)    // 8192
#define NZ (BATCHX * NUM_HEADSX) // 64

// ---- static device scratch ----
__device__ float  g_Q[(size_t)M_TOK * D_MODELX];
__device__ float  g_K[(size_t)M_TOK * D_MODELX];
__device__ __half g_Vth[(size_t)M_TOK * D_MODELX];  // [Z][64][2048] fp16 hi
__device__ __half g_Vtl[(size_t)M_TOK * D_MODELX];  // [Z][64][2048] fp16 lo
__device__ float  g_O[(size_t)M_TOK * D_MODELX];
__device__ float  g_P[(size_t)NZ * SEQX * SEQX];    // 1 GiB raw scores
__device__ __half g_Ph[(size_t)NZ * SEQX * SEQX];   // 0.5 GiB fp16 probs

__device__ __forceinline__ unsigned pack_bf2(float x, float y) {
    __nv_bfloat162 t = __floats2bfloat162_rn(x, y);
    return *reinterpret_cast<unsigned*>(&t);
}

#define MMA_BF16(c, a0, a1, a2, a3, b0, b1)                                   \
    asm volatile(                                                             \
        "mma.sync.aligned.m16n8k16.row.col.f32.bf16.bf16.f32 "                \
        "{%0,%1,%2,%3},{%4,%5,%6,%7},{%8,%9},{%0,%1,%2,%3};"                  \
        : "+f"(c[0]), "+f"(c[1]), "+f"(c[2]), "+f"(c[3])                      \
        : "r"(a0), "r"(a1), "r"(a2), "r"(a3), "r"(b0), "r"(b1))

#define MMA_F16(c, a0, a1, a2, a3, b0, b1)                                    \
    asm volatile(                                                             \
        "mma.sync.aligned.m16n8k16.row.col.f32.f16.f16.f32 "                  \
        "{%0,%1,%2,%3},{%4,%5,%6,%7},{%8,%9},{%0,%1,%2,%3};"                  \
        : "+f"(c[0]), "+f"(c[1]), "+f"(c[2]), "+f"(c[3])                      \
        : "r"(a0), "r"(a1), "r"(a2), "r"(a3), "r"(b0), "r"(b1))

// ============================================================================
// NT bf16-split MMA GEMM: C = alpha * (A @ B^T) + bias  (fp32 in, split in-kernel)
// MODE 0: plain fp32 out + bias
// MODE 1: scores  — z head offsets; C = fp32 P[z] * alpha
// MODE 3: V projection, transposed fp16 hi/lo store into [Z][64][2048]
// Block tile 128x64x32, 256 threads (8 warps 4x2), warp tile 32x32.
// ============================================================================
template <int MODE>
__global__ __launch_bounds__(256)
void mma_gemm(const float* __restrict__ A,
              const float* __restrict__ B,
              float* __restrict__ C,
              __half* __restrict__ Ch, __half* __restrict__ Cl,
              int lda, int ldb, int ldc,
              int K, float alpha,
              const float* __restrict__ bias)
{
    constexpr int BM = 128, BN = 64, BK = 32;
    constexpr int SA = 40;

    __shared__ __align__(16) __nv_bfloat16 AsH[BM * SA];
    __shared__ __align__(16) __nv_bfloat16 AsL[BM * SA];
    __shared__ __align__(16) __nv_bfloat16 BsH[BN * SA];
    __shared__ __align__(16) __nv_bfloat16 BsL[BN * SA];

    if (MODE == 1) {
        int z = blockIdx.z, b = z >> 4, h = z & 15;
        A += (size_t)b * SEQX * D_MODELX + h * D_HEADX;
        B += (size_t)b * SEQX * D_MODELX + h * D_HEADX;
        C += (size_t)z * SEQX * SEQX;
    }

    const int tid  = threadIdx.x;
    const int m0   = blockIdx.y * BM;
    const int n0   = blockIdx.x * BN;
    const int warp = tid >> 5, lane = tid & 31;
    const int wm = (warp & 3) * 32;
    const int wn = (warp >> 2) * 32;
    const int gr = lane >> 2;
    const int gc = lane & 3;

    float acc[2][4][4] = {};
    float4 ra[4], rb[2];

    {
        #pragma unroll
        for (int i = 0; i < 4; i++) {
            int idx = tid + i * 256, row = idx >> 3, c4 = idx & 7;
            ra[i] = *(const float4*)(A + (size_t)(m0 + row) * lda + c4 * 4);
        }
        #pragma unroll
        for (int i = 0; i < 2; i++) {
            int idx = tid + i * 256, row = idx >> 3, c4 = idx & 7;
            rb[i] = *(const float4*)(B + (size_t)(n0 + row) * ldb + c4 * 4);
        }
    }

    const int niter = K / BK;
    for (int it = 0; it < niter; ++it) {
        #pragma unroll
        for (int i = 0; i < 4; i++) {
            int idx = tid + i * 256, row = idx >> 3, c4 = idx & 7;
            float v0 = ra[i].x, v1 = ra[i].y, v2 = ra[i].z, v3 = ra[i].w;
            float h0 = __bfloat162float(__float2bfloat16_rn(v0));
            float h1 = __bfloat162float(__float2bfloat16_rn(v1));
            float h2 = __bfloat162float(__float2bfloat16_rn(v2));
            float h3 = __bfloat162float(__float2bfloat16_rn(v3));
            uint2 H, L;
            H.x = pack_bf2(v0, v1); H.y = pack_bf2(v2, v3);
            L.x = pack_bf2(v0 - h0, v1 - h1); L.y = pack_bf2(v2 - h2, v3 - h3);
            *(uint2*)&AsH[row * SA + c4 * 4] = H;
            *(uint2*)&AsL[row * SA + c4 * 4] = L;
        }
        #pragma unroll
        for (int i = 0; i < 2; i++) {
            int idx = tid + i * 256, row = idx >> 3, c4 = idx & 7;
            float v0 = rb[i].x, v1 = rb[i].y, v2 = rb[i].z, v3 = rb[i].w;
            float h0 = __bfloat162float(__float2bfloat16_rn(v0));
            float h1 = __bfloat162float(__float2bfloat16_rn(v1));
            float h2 = __bfloat162float(__float2bfloat16_rn(v2));
            float h3 = __bfloat162float(__float2bfloat16_rn(v3));
            uint2 H, L;
            H.x = pack_bf2(v0, v1); H.y = pack_bf2(v2, v3);
            L.x = pack_bf2(v0 - h0, v1 - h1); L.y = pack_bf2(v2 - h2, v3 - h3);
            *(uint2*)&BsH[row * SA + c4 * 4] = H;
            *(uint2*)&BsL[row * SA + c4 * 4] = L;
        }
        __syncthreads();

        if (it + 1 < niter) {
            int k0 = (it + 1) * BK;
            #pragma unroll
            for (int i = 0; i < 4; i++) {
                int idx = tid + i * 256, row = idx >> 3, c4 = idx & 7;
                ra[i] = *(const float4*)(A + (size_t)(m0 + row) * lda + k0 + c4 * 4);
            }
            #pragma unroll
            for (int i = 0; i < 2; i++) {
                int idx = tid + i * 256, row = idx >> 3, c4 = idx & 7;
                rb[i] = *(const float4*)(B + (size_t)(n0 + row) * ldb + k0 + c4 * 4);
            }
        }

        #pragma unroll
        for (int ks = 0; ks < 2; ks++) {
            const int kb = ks * 16;
            unsigned aH[2][4], aL[2][4], bH[4][2], bL[4][2];
            #pragma unroll
            for (int mi = 0; mi < 2; mi++) {
                int r = (wm + mi * 16 + gr) * SA + kb + gc * 2;
                aH[mi][0] = *(const unsigned*)&AsH[r];
                aH[mi][1] = *(const unsigned*)&AsH[r + 8 * SA];
                aH[mi][2] = *(const unsigned*)&AsH[r + 8];
                aH[mi][3] = *(const unsigned*)&AsH[r + 8 * SA + 8];
                aL[mi][0] = *(const unsigned*)&AsL[r];
                aL[mi][1] = *(const unsigned*)&AsL[r + 8 * SA];
                aL[mi][2] = *(const unsigned*)&AsL[r + 8];
                aL[mi][3] = *(const unsigned*)&AsL[r + 8 * SA + 8];
            }
            #pragma unroll
            for (int ni = 0; ni < 4; ni++) {
                int r = (wn + ni * 8 + gr) * SA + kb + gc * 2;
                bH[ni][0] = *(const unsigned*)&BsH[r];
                bH[ni][1] = *(const unsigned*)&BsH[r + 8];
                bL[ni][0] = *(const unsigned*)&BsL[r];
                bL[ni][1] = *(const unsigned*)&BsL[r + 8];
            }
            #pragma unroll
            for (int mi = 0; mi < 2; mi++)
                #pragma unroll
                for (int ni = 0; ni < 4; ni++) {
                    MMA_BF16(acc[mi][ni], aH[mi][0], aH[mi][1], aH[mi][2], aH[mi][3],
                             bH[ni][0], bH[ni][1]);
                    MMA_BF16(acc[mi][ni], aH[mi][0], aH[mi][1], aH[mi][2], aH[mi][3],
                             bL[ni][0], bL[ni][1]);
                    MMA_BF16(acc[mi][ni], aL[mi][0], aL[mi][1], aL[mi][2], aL[mi][3],
                             bH[ni][0], bH[ni][1]);
                }
        }
        __syncthreads();
    }

    #pragma unroll
    for (int mi = 0; mi < 2; mi++)
        #pragma unroll
        for (int ni = 0; ni < 4; ni++) {
            int r = m0 + wm + mi * 16 + gr;
            int c = n0 + wn + ni * 8 + gc * 2;
            float* cc = acc[mi][ni];
            if (MODE == 3) {
                // transposed fp16 hi/lo store into Vt [Z][64][2048]
                int b = r >> 11, s = r & 2047;
                int h = c >> 6, d = c & 63;
                float b0 = bias[c], b1 = bias[c + 1];
                float v00 = cc[0] + b0, v01 = cc[1] + b1;
                float v10 = cc[2] + b0, v11 = cc[3] + b1;
                size_t base = ((size_t)(b * 16 + h) * 64 + d) * 2048;
                __half h00 = __float2half_rn(v00);
                __half h01 = __float2half_rn(v01);
                __half h10 = __float2half_rn(v10);
                __half h11 = __float2half_rn(v11);
                Ch[base + s]            = h00;
                Ch[base + 2048 + s]     = h01;
                Ch[base + s + 8]        = h10;
                Ch[base + 2048 + s + 8] = h11;
                Cl[base + s]            = __float2half_rn(v00 - __half2float(h00));
                Cl[base + 2048 + s]     = __float2half_rn(v01 - __half2float(h01));
                Cl[base + s + 8]        = __float2half_rn(v10 - __half2float(h10));
                Cl[base + 2048 + s + 8] = __float2half_rn(v11 - __half2float(h11));
            } else if (MODE == 1) {
                float2 v0 = make_float2(cc[0] * alpha, cc[1] * alpha);
                float2 v1 = make_float2(cc[2] * alpha, cc[3] * alpha);
                *(float2*)&C[(size_t)r * ldc + c]       = v0;
                *(float2*)&C[(size_t)(r + 8) * ldc + c] = v1;
            } else {
                float b0 = 0.f, b1 = 0.f;
                if (bias) { b0 = bias[c]; b1 = bias[c + 1]; }
                float2 v0 = make_float2(cc[0] + b0, cc[1] + b1);
                float2 v1 = make_float2(cc[2] + b0, cc[3] + b1);
                *(float2*)&C[(size_t)r * ldc + c]       = v0;
                *(float2*)&C[(size_t)(r + 8) * ldc + c] = v1;
            }
        }
}

// ============================================================================
// stats + head-average: per (b,q), softmax each head row, write fp16 probs
// and fp32 head-averaged row. float2/half2 vectorized.
// ============================================================================
__global__ __launch_bounds__(256)
void stats_avg_kernel(const float* __restrict__ P, __half* __restrict__ Ph,
                      float* __restrict__ avg)
{
    __shared__ float red[8];
    const int bq = blockIdx.x;
    const int t  = threadIdx.x;
    const int b  = bq >> 11;
    const int q  = bq & 2047;

    float avgacc[8] = {};

    for (int h = 0; h < NUM_HEADSX; ++h) {
        const int z = b * 16 + h;
        const float2* p2 = (const float2*)(P + ((size_t)z * SEQX + q) * SEQX);
        __half2* o2 = (__half2*)(Ph + ((size_t)z * SEQX + q) * SEQX);

        float2 v[4];
        float mx = -1e30f;
        #pragma unroll
        for (int i = 0; i < 4; i++) {
            v[i] = p2[t + i * 256];
            mx = fmaxf(mx, fmaxf(v[i].x, v[i].y));
        }
        #pragma unroll
        for (int o = 16; o > 0; o >>= 1)
            mx = fmaxf(mx, __shfl_xor_sync(0xffffffffu, mx, o));
        if ((t & 31) == 0) red[t >> 5] = mx;
        __syncthreads();
        float bm = red[0];
        #pragma unroll
        for (int w = 1; w < 8; w++) bm = fmaxf(bm, red[w]);
        __syncthreads();

        float s = 0.f;
        #pragma unroll
        for (int i = 0; i < 4; i++) {
            v[i].x = __expf(v[i].x - bm);
            v[i].y = __expf(v[i].y - bm);
            s += v[i].x + v[i].y;
        }
        #pragma unroll
        for (int o = 16; o > 0; o >>= 1)
            s += __shfl_xor_sync(0xffffffffu, s, o);
        if ((t & 31) == 0) red[t >> 5] = s;
        __syncthreads();
        float bs = 0.f;
        #pragma unroll
        for (int w = 0; w < 8; w++) bs += red[w];
        float inv = 1.0f / bs;

        #pragma unroll
        for (int i = 0; i < 4; i++) {
            float px = v[i].x * inv, py = v[i].y * inv;
            o2[t + i * 256] = __floats2half2_rn(px, py);
            avgacc[2 * i]     += px;
            avgacc[2 * i + 1] += py;
        }
        __syncthreads();
    }

    float2* a2 = (float2*)(avg + (size_t)bq * SEQX);
    #pragma unroll
    for (int i = 0; i < 4; i++)
        a2[t + i * 256] = make_float2(avgacc[2 * i] * (1.0f / NUM_HEADSX),
                                      avgacc[2 * i + 1] * (1.0f / NUM_HEADSX));
}

// ============================================================================
// AV: O_h = P_h(fp16 probs) @ Vt_h^T (fp16 hi/lo), fp32 acc. Pure fp16 HMMA.
// M=2048 per z, N=64, K=2048. Block 128x64x64, 256 threads.
// ============================================================================
__global__ __launch_bounds__(256)
void av_gemm(const __half* __restrict__ P,
             const __half* __restrict__ Vh, const __half* __restrict__ Vl,
             float* __restrict__ O)
{
    constexpr int BM = 128, BN = 64, BK = 64;
    constexpr int SA = 72;

    __shared__ __align__(16) __half As[BM * SA];
    __shared__ __align__(16) __half BsH[BN * SA];
    __shared__ __align__(16) __half BsL[BN * SA];

    const int z = blockIdx.z, b = z >> 4, h = z & 15;
    P  += (size_t)z * SEQX * SEQX;
    Vh += (size_t)z * D_HEADX * SEQX;
    Vl += (size_t)z * D_HEADX * SEQX;
    O  += (size_t)b * SEQX * D_MODELX + h * D_HEADX;

    const int tid  = threadIdx.x;
    const int m0   = blockIdx.y * BM;
    const int warp = tid >> 5, lane = tid & 31;
    const int wm = (warp & 3) * 32;
    const int wn = (warp >> 2) * 32;
    const int gr = lane >> 2;
    const int gc = lane & 3;

    float acc[2][4][4] = {};
    uint4 pa[4], pbh[2], pbl[2];

    {
        #pragma unroll
        for (int i = 0; i < 4; i++) {
            int idx = tid + i * 256, row = idx >> 3, c8 = idx & 7;
            pa[i] = *(const uint4*)(P + (size_t)(m0 + row) * SEQX + c8 * 8);
        }
        #pragma unroll
        for (int i = 0; i < 2; i++) {
            int idx = tid + i * 256, row = idx >> 3, c8 = idx & 7;
            pbh[i] = *(const uint4*)(Vh + (size_t)row * SEQX + c8 * 8);
            pbl[i] = *(const uint4*)(Vl + (size_t)row * SEQX + c8 * 8);
        }
    }

    const int niter = SEQX / BK;  // 32
    for (int it = 0; it < niter; ++it) {
        #pragma unroll
        for (int i = 0; i < 4; i++) {
            int idx = tid + i * 256, row = idx >> 3, c8 = idx & 7;
            *(uint4*)&As[row * SA + c8 * 8] = pa[i];
        }
        #pragma unroll
        for (int i = 0; i < 2; i++) {
            int idx = tid + i * 256, row = idx >> 3, c8 = idx & 7;
            *(uint4*)&BsH[row * SA + c8 * 8] = pbh[i];
            *(uint4*)&BsL[row * SA + c8 * 8] = pbl[i];
        }
        __syncthreads();

        if (it + 1 < niter) {
            int k0 = (it + 1) * BK;
            #pragma unroll
            for (int i = 0; i < 4; i++) {
                int idx = tid + i * 256, row = idx >> 3, c8 = idx & 7;
                pa[i] = *(const uint4*)(P + (size_t)(m0 + row) * SEQX + k0 + c8 * 8);
            }
            #pragma unroll
            for (int i = 0; i < 2; i++) {
                int idx = tid + i * 256, row = idx >> 3, c8 = idx & 7;
                pbh[i] = *(const uint4*)(Vh + (size_t)row * SEQX + k0 + c8 * 8);
                pbl[i] = *(const uint4*)(Vl + (size_t)row * SEQX + k0 + c8 * 8);
            }
        }

        #pragma unroll
        for (int ks = 0; ks < 4; ks++) {
            const int kb = ks * 16;
            unsigned a[2][4], bH[4][2], bL[4][2];
            #pragma unroll
            for (int mi = 0; mi < 2; mi++) {
                int r = (wm + mi * 16 + gr) * SA + kb + gc * 2;
                a[mi][0] = *(const unsigned*)&As[r];
                a[mi][1] = *(const unsigned*)&As[r + 8 * SA];
                a[mi][2] = *(const unsigned*)&As[r + 8];
                a[mi][3] = *(const unsigned*)&As[r + 8 * SA + 8];
            }
            #pragma unroll
            for (int ni = 0; ni < 4; ni++) {
                int r = (wn + ni * 8 + gr) * SA + kb + gc * 2;
                bH[ni][0] = *(const unsigned*)&BsH[r];
                bH[ni][1] = *(const unsigned*)&BsH[r + 8];
                bL[ni][0] = *(const unsigned*)&BsL[r];
                bL[ni][1] = *(const unsigned*)&BsL[r + 8];
            }
            #pragma unroll
            for (int mi = 0; mi < 2; mi++)
                #pragma unroll
                for (int ni = 0; ni < 4; ni++) {
                    MMA_F16(acc[mi][ni], a[mi][0], a[mi][1], a[mi][2], a[mi][3],
                            bH[ni][0], bH[ni][1]);
                    MMA_F16(acc[mi][ni], a[mi][0], a[mi][1], a[mi][2], a[mi][3],
                            bL[ni][0], bL[ni][1]);
                }
        }
        __syncthreads();
    }

    #pragma unroll
    for (int mi = 0; mi < 2; mi++)
        #pragma unroll
        for (int ni = 0; ni < 4; ni++) {
            int r = m0 + wm + mi * 16 + gr;
            int c = wn + ni * 8 + gc * 2;
            float* cc = acc[mi][ni];
            *(float2*)&O[(size_t)r * D_MODELX + c]       = make_float2(cc[0], cc[1]);
            *(float2*)&O[(size_t)(r + 8) * D_MODELX + c] = make_float2(cc[2], cc[3]);
        }
}

// ============================================================================
// launch
// ============================================================================
extern "C" void kernel_launch(void* const* d_in, const int* in_sizes, int n_in,
                              void* d_out, int out_size)
{
    const float* x_q = (const float*)d_in[0];
    const float* x_k = (const float*)d_in[1];
    const float* x_v = (const float*)d_in[2];
    const float* Wq  = (const float*)d_in[3];
    const float* bq  = (const float*)d_in[4];
    const float* Wk  = (const float*)d_in[5];
    const float* bk  = (const float*)d_in[6];
    const float* Wv  = (const float*)d_in[7];
    const float* bv  = (const float*)d_in[8];
    const float* Wo  = (const float*)d_in[9];
    const float* bo  = (const float*)d_in[10];

    float* out = (float*)d_out;
    float* avg = out + (size_t)M_TOK * D_MODELX;

    float *gQ, *gK, *gO, *P;
    __half *Vth, *Vtl, *Ph;
    cudaGetSymbolAddress((void**)&gQ, g_Q);
    cudaGetSymbolAddress((void**)&gK, g_K);
    cudaGetSymbolAddress((void**)&gO, g_O);
    cudaGetSymbolAddress((void**)&P, g_P);
    cudaGetSymbolAddress((void**)&Vth, g_Vth);
    cudaGetSymbolAddress((void**)&Vtl, g_Vtl);
    cudaGetSymbolAddress((void**)&Ph, g_Ph);

    dim3 blk(256);
    dim3 gproj(D_MODELX / 64, M_TOK / 128, 1);   // (16, 64)

    // 1-3) projections (V transposed fp16 hi/lo out)
    mma_gemm<0><<<gproj, blk>>>(x_q, Wq, gQ, nullptr, nullptr,
                                D_MODELX, D_MODELX, D_MODELX, D_MODELX, 1.0f, bq);
    mma_gemm<0><<<gproj, blk>>>(x_k, Wk, gK, nullptr, nullptr,
                                D_MODELX, D_MODELX, D_MODELX, D_MODELX, 1.0f, bk);
    mma_gemm<3><<<gproj, blk>>>(x_v, Wv, nullptr, Vth, Vtl,
                                D_MODELX, D_MODELX, 0, D_MODELX, 1.0f, bv);

    // 4) scores: raw P = (Q_h @ K_h^T) / 8
    dim3 gsc(SEQX / 64, SEQX / 128, NZ);         // (32, 16, 64)
    mma_gemm<1><<<gsc, blk>>>(gQ, gK, P, nullptr, nullptr,
                              D_MODELX, D_MODELX, SEQX, D_HEADX, 0.125f, nullptr);

    // 5) softmax stats + fp16 probs + head-average
    stats_avg_kernel<<<M_TOK, blk>>>(P, Ph, avg);

    // 6) AV fp16 MMA
    dim3 gav(1, SEQX / 128, NZ);                 // (1, 16, 64)
    av_gemm<<<gav, blk>>>(Ph, Vth, Vtl, gO);

    // 7) output projection
    mma_gemm<0><<<gproj, blk>>>(gO, Wo, out, nullptr, nullptr,
                                D_MODELX, D_MODELX, D_MODELX, D_MODELX, 1.0f, bo);
}

// round 5
// speedup vs baseline: 1.2528x; 1.0735x over previous
#include <cuda_runtime.h>
#include <cuda_bf16.h>
#include <cuda_fp16.h>
#include <cstdint>

#define D_MODELX 1024
#define NUM_HEADSX 16
#define D_HEADX 64
#define BATCHX 4
#define SEQX 2048
#define M_TOK (BATCHX * SEQX)    // 8192
#define NZ (BATCHX * NUM_HEADSX) // 64

// ---- static device scratch ----
__device__ __nv_bfloat16 g_Qh[(size_t)M_TOK * D_MODELX];
__device__ __nv_bfloat16 g_Ql[(size_t)M_TOK * D_MODELX];
__device__ __nv_bfloat16 g_Kh[(size_t)M_TOK * D_MODELX];
__device__ __nv_bfloat16 g_Kl[(size_t)M_TOK * D_MODELX];
__device__ __half g_Vth[(size_t)M_TOK * D_MODELX];  // [Z][64][2048] fp16 hi
__device__ __half g_Vtl[(size_t)M_TOK * D_MODELX];  // [Z][64][2048] fp16 lo
__device__ float  g_O[(size_t)M_TOK * D_MODELX];
__device__ float  g_P[(size_t)NZ * SEQX * SEQX];    // 1 GiB raw scores
__device__ __half g_Ph[(size_t)NZ * SEQX * SEQX];   // 0.5 GiB fp16 probs

__device__ __forceinline__ unsigned pack_bf2(float x, float y) {
    __nv_bfloat162 t = __floats2bfloat162_rn(x, y);
    return *reinterpret_cast<unsigned*>(&t);
}

#define MMA_BF16(c, a0, a1, a2, a3, b0, b1)                                   \
    asm volatile(                                                             \
        "mma.sync.aligned.m16n8k16.row.col.f32.bf16.bf16.f32 "                \
        "{%0,%1,%2,%3},{%4,%5,%6,%7},{%8,%9},{%0,%1,%2,%3};"                  \
        : "+f"(c[0]), "+f"(c[1]), "+f"(c[2]), "+f"(c[3])                      \
        : "r"(a0), "r"(a1), "r"(a2), "r"(a3), "r"(b0), "r"(b1))

#define MMA_F16(c, a0, a1, a2, a3, b0, b1)                                    \
    asm volatile(                                                             \
        "mma.sync.aligned.m16n8k16.row.col.f32.f16.f16.f32 "                  \
        "{%0,%1,%2,%3},{%4,%5,%6,%7},{%8,%9},{%0,%1,%2,%3};"                  \
        : "+f"(c[0]), "+f"(c[1]), "+f"(c[2]), "+f"(c[3])                      \
        : "r"(a0), "r"(a1), "r"(a2), "r"(a3), "r"(b0), "r"(b1))

// ============================================================================
// NT bf16-split MMA GEMM (fp32 in, split in-kernel): C = A @ B^T + bias
// MODE 0: fp32 out + bias (output projection)
// MODE 3: V projection, transposed fp16 hi/lo store into [Z][64][2048]
// MODE 5: Q/K projection, bf16 hi/lo out + bias
// Block tile 128x64x32, 256 threads (8 warps 4x2), warp tile 32x32.
// ============================================================================
template <int MODE>
__global__ __launch_bounds__(256)
void mma_gemm(const float* __restrict__ A,
              const float* __restrict__ B,
              float* __restrict__ C,
              void* __restrict__ Chv, void* __restrict__ Clv,
              int lda, int ldb, int ldc,
              int K, const float* __restrict__ bias)
{
    constexpr int BM = 128, BN = 64, BK = 32;
    constexpr int SA = 40;

    __shared__ __align__(16) __nv_bfloat16 AsH[BM * SA];
    __shared__ __align__(16) __nv_bfloat16 AsL[BM * SA];
    __shared__ __align__(16) __nv_bfloat16 BsH[BN * SA];
    __shared__ __align__(16) __nv_bfloat16 BsL[BN * SA];

    const int tid  = threadIdx.x;
    const int m0   = blockIdx.y * BM;
    const int n0   = blockIdx.x * BN;
    const int warp = tid >> 5, lane = tid & 31;
    const int wm = (warp & 3) * 32;
    const int wn = (warp >> 2) * 32;
    const int gr = lane >> 2;
    const int gc = lane & 3;

    float acc[2][4][4] = {};
    float4 ra[4], rb[2];

    {
        #pragma unroll
        for (int i = 0; i < 4; i++) {
            int idx = tid + i * 256, row = idx >> 3, c4 = idx & 7;
            ra[i] = *(const float4*)(A + (size_t)(m0 + row) * lda + c4 * 4);
        }
        #pragma unroll
        for (int i = 0; i < 2; i++) {
            int idx = tid + i * 256, row = idx >> 3, c4 = idx & 7;
            rb[i] = *(const float4*)(B + (size_t)(n0 + row) * ldb + c4 * 4);
        }
    }

    const int niter = K / BK;
    for (int it = 0; it < niter; ++it) {
        #pragma unroll
        for (int i = 0; i < 4; i++) {
            int idx = tid + i * 256, row = idx >> 3, c4 = idx & 7;
            float v0 = ra[i].x, v1 = ra[i].y, v2 = ra[i].z, v3 = ra[i].w;
            float h0 = __bfloat162float(__float2bfloat16_rn(v0));
            float h1 = __bfloat162float(__float2bfloat16_rn(v1));
            float h2 = __bfloat162float(__float2bfloat16_rn(v2));
            float h3 = __bfloat162float(__float2bfloat16_rn(v3));
            uint2 H, L;
            H.x = pack_bf2(v0, v1); H.y = pack_bf2(v2, v3);
            L.x = pack_bf2(v0 - h0, v1 - h1); L.y = pack_bf2(v2 - h2, v3 - h3);
            *(uint2*)&AsH[row * SA + c4 * 4] = H;
            *(uint2*)&AsL[row * SA + c4 * 4] = L;
        }
        #pragma unroll
        for (int i = 0; i < 2; i++) {
            int idx = tid + i * 256, row = idx >> 3, c4 = idx & 7;
            float v0 = rb[i].x, v1 = rb[i].y, v2 = rb[i].z, v3 = rb[i].w;
            float h0 = __bfloat162float(__float2bfloat16_rn(v0));
            float h1 = __bfloat162float(__float2bfloat16_rn(v1));
            float h2 = __bfloat162float(__float2bfloat16_rn(v2));
            float h3 = __bfloat162float(__float2bfloat16_rn(v3));
            uint2 H, L;
            H.x = pack_bf2(v0, v1); H.y = pack_bf2(v2, v3);
            L.x = pack_bf2(v0 - h0, v1 - h1); L.y = pack_bf2(v2 - h2, v3 - h3);
            *(uint2*)&BsH[row * SA + c4 * 4] = H;
            *(uint2*)&BsL[row * SA + c4 * 4] = L;
        }
        __syncthreads();

        if (it + 1 < niter) {
            int k0 = (it + 1) * BK;
            #pragma unroll
            for (int i = 0; i < 4; i++) {
                int idx = tid + i * 256, row = idx >> 3, c4 = idx & 7;
                ra[i] = *(const float4*)(A + (size_t)(m0 + row) * lda + k0 + c4 * 4);
            }
            #pragma unroll
            for (int i = 0; i < 2; i++) {
                int idx = tid + i * 256, row = idx >> 3, c4 = idx & 7;
                rb[i] = *(const float4*)(B + (size_t)(n0 + row) * ldb + k0 + c4 * 4);
            }
        }

        #pragma unroll
        for (int ks = 0; ks < 2; ks++) {
            const int kb = ks * 16;
            unsigned aH[2][4], aL[2][4], bH[4][2], bL[4][2];
            #pragma unroll
            for (int mi = 0; mi < 2; mi++) {
                int r = (wm + mi * 16 + gr) * SA + kb + gc * 2;
                aH[mi][0] = *(const unsigned*)&AsH[r];
                aH[mi][1] = *(const unsigned*)&AsH[r + 8 * SA];
                aH[mi][2] = *(const unsigned*)&AsH[r + 8];
                aH[mi][3] = *(const unsigned*)&AsH[r + 8 * SA + 8];
                aL[mi][0] = *(const unsigned*)&AsL[r];
                aL[mi][1] = *(const unsigned*)&AsL[r + 8 * SA];
                aL[mi][2] = *(const unsigned*)&AsL[r + 8];
                aL[mi][3] = *(const unsigned*)&AsL[r + 8 * SA + 8];
            }
            #pragma unroll
            for (int ni = 0; ni < 4; ni++) {
                int r = (wn + ni * 8 + gr) * SA + kb + gc * 2;
                bH[ni][0] = *(const unsigned*)&BsH[r];
                bH[ni][1] = *(const unsigned*)&BsH[r + 8];
                bL[ni][0] = *(const unsigned*)&BsL[r];
                bL[ni][1] = *(const unsigned*)&BsL[r + 8];
            }
            #pragma unroll
            for (int mi = 0; mi < 2; mi++)
                #pragma unroll
                for (int ni = 0; ni < 4; ni++) {
                    MMA_BF16(acc[mi][ni], aH[mi][0], aH[mi][1], aH[mi][2], aH[mi][3],
                             bH[ni][0], bH[ni][1]);
                    MMA_BF16(acc[mi][ni], aH[mi][0], aH[mi][1], aH[mi][2], aH[mi][3],
                             bL[ni][0], bL[ni][1]);
                    MMA_BF16(acc[mi][ni], aL[mi][0], aL[mi][1], aL[mi][2], aL[mi][3],
                             bH[ni][0], bH[ni][1]);
                }
        }
        __syncthreads();
    }

    #pragma unroll
    for (int mi = 0; mi < 2; mi++)
        #pragma unroll
        for (int ni = 0; ni < 4; ni++) {
            int r = m0 + wm + mi * 16 + gr;
            int c = n0 + wn + ni * 8 + gc * 2;
            float* cc = acc[mi][ni];
            if (MODE == 3) {
                __half* Ch = (__half*)Chv;
                __half* Cl = (__half*)Clv;
                int b = r >> 11, s = r & 2047;
                int h = c >> 6, d = c & 63;
                float b0 = bias[c], b1 = bias[c + 1];
                float v00 = cc[0] + b0, v01 = cc[1] + b1;
                float v10 = cc[2] + b0, v11 = cc[3] + b1;
                size_t base = ((size_t)(b * 16 + h) * 64 + d) * 2048;
                __half h00 = __float2half_rn(v00);
                __half h01 = __float2half_rn(v01);
                __half h10 = __float2half_rn(v10);
                __half h11 = __float2half_rn(v11);
                Ch[base + s]            = h00;
                Ch[base + 2048 + s]     = h01;
                Ch[base + s + 8]        = h10;
                Ch[base + 2048 + s + 8] = h11;
                Cl[base + s]            = __float2half_rn(v00 - __half2float(h00));
                Cl[base + 2048 + s]     = __float2half_rn(v01 - __half2float(h01));
                Cl[base + s + 8]        = __float2half_rn(v10 - __half2float(h10));
                Cl[base + 2048 + s + 8] = __float2half_rn(v11 - __half2float(h11));
            } else if (MODE == 5) {
                __nv_bfloat16* Ch = (__nv_bfloat16*)Chv;
                __nv_bfloat16* Cl = (__nv_bfloat16*)Clv;
                float b0 = bias[c], b1 = bias[c + 1];
                float v00 = cc[0] + b0, v01 = cc[1] + b1;
                float v10 = cc[2] + b0, v11 = cc[3] + b1;
                float h00 = __bfloat162float(__float2bfloat16_rn(v00));
                float h01 = __bfloat162float(__float2bfloat16_rn(v01));
                float h10 = __bfloat162float(__float2bfloat16_rn(v10));
                float h11 = __bfloat162float(__float2bfloat16_rn(v11));
                size_t o0 = (size_t)r * ldc + c;
                size_t o1 = (size_t)(r + 8) * ldc + c;
                *(unsigned*)&Ch[o0] = pack_bf2(v00, v01);
                *(unsigned*)&Ch[o1] = pack_bf2(v10, v11);
                *(unsigned*)&Cl[o0] = pack_bf2(v00 - h00, v01 - h01);
                *(unsigned*)&Cl[o1] = pack_bf2(v10 - h10, v11 - h11);
            } else {
                float b0 = 0.f, b1 = 0.f;
                if (bias) { b0 = bias[c]; b1 = bias[c + 1]; }
                float2 v0 = make_float2(cc[0] + b0, cc[1] + b1);
                float2 v1 = make_float2(cc[2] + b0, cc[3] + b1);
                *(float2*)&C[(size_t)r * ldc + c]       = v0;
                *(float2*)&C[(size_t)(r + 8) * ldc + c] = v1;
            }
        }
}

// ============================================================================
// Scores: P[z] = (Q_h @ K_h^T)/8, pure pre-split bf16. K=64 -> single smem
// load, no k-loop. Block tile 128x128, 8 warps (4M x 2N), warp tile 32x64.
// ============================================================================
__global__ __launch_bounds__(256)
void scores_gemm(const __nv_bfloat16* __restrict__ Qh, const __nv_bfloat16* __restrict__ Ql,
                 const __nv_bfloat16* __restrict__ Kh, const __nv_bfloat16* __restrict__ Kl,
                 float* __restrict__ P)
{
    constexpr int SA = 72;
    __shared__ __align__(16) __nv_bfloat16 AsH[128 * SA];
    __shared__ __align__(16) __nv_bfloat16 AsL[128 * SA];
    __shared__ __align__(16) __nv_bfloat16 BsH[128 * SA];
    __shared__ __align__(16) __nv_bfloat16 BsL[128 * SA];

    const int z = blockIdx.z, b = z >> 4, h = z & 15;
    const size_t qo = (size_t)b * SEQX * D_MODELX + h * D_HEADX;
    Qh += qo; Ql += qo; Kh += qo; Kl += qo;
    P += (size_t)z * SEQX * SEQX;

    const int tid  = threadIdx.x;
    const int m0   = blockIdx.y * 128;
    const int n0   = blockIdx.x * 128;
    const int warp = tid >> 5, lane = tid & 31;
    const int wm = (warp & 3) * 32;
    const int wn = (warp >> 2) * 64;
    const int gr = lane >> 2;
    const int gc = lane & 3;

    #pragma unroll
    for (int i = 0; i < 4; i++) {
        int idx = tid + i * 256, row = idx >> 3, c8 = idx & 7;
        size_t oa = (size_t)(m0 + row) * D_MODELX + c8 * 8;
        size_t ob = (size_t)(n0 + row) * D_MODELX + c8 * 8;
        *(uint4*)&AsH[row * SA + c8 * 8] = *(const uint4*)(Qh + oa);
        *(uint4*)&AsL[row * SA + c8 * 8] = *(const uint4*)(Ql + oa);
        *(uint4*)&BsH[row * SA + c8 * 8] = *(const uint4*)(Kh + ob);
        *(uint4*)&BsL[row * SA + c8 * 8] = *(const uint4*)(Kl + ob);
    }
    __syncthreads();

    float acc[2][8][4] = {};

    #pragma unroll
    for (int ks = 0; ks < 4; ks++) {
        const int kb = ks * 16;
        unsigned aH[2][4], aL[2][4];
        #pragma unroll
        for (int mi = 0; mi < 2; mi++) {
            int r = (wm + mi * 16 + gr) * SA + kb + gc * 2;
            aH[mi][0] = *(const unsigned*)&AsH[r];
            aH[mi][1] = *(const unsigned*)&AsH[r + 8 * SA];
            aH[mi][2] = *(const unsigned*)&AsH[r + 8];
            aH[mi][3] = *(const unsigned*)&AsH[r + 8 * SA + 8];
            aL[mi][0] = *(const unsigned*)&AsL[r];
            aL[mi][1] = *(const unsigned*)&AsL[r + 8 * SA];
            aL[mi][2] = *(const unsigned*)&AsL[r + 8];
            aL[mi][3] = *(const unsigned*)&AsL[r + 8 * SA + 8];
        }
        #pragma unroll
        for (int ni = 0; ni < 8; ni++) {
            int r = (wn + ni * 8 + gr) * SA + kb + gc * 2;
            unsigned b0 = *(const unsigned*)&BsH[r];
            unsigned b1 = *(const unsigned*)&BsH[r + 8];
            unsigned l0 = *(const unsigned*)&BsL[r];
            unsigned l1 = *(const unsigned*)&BsL[r + 8];
            #pragma unroll
            for (int mi = 0; mi < 2; mi++) {
                MMA_BF16(acc[mi][ni], aH[mi][0], aH[mi][1], aH[mi][2], aH[mi][3], b0, b1);
                MMA_BF16(acc[mi][ni], aH[mi][0], aH[mi][1], aH[mi][2], aH[mi][3], l0, l1);
                MMA_BF16(acc[mi][ni], aL[mi][0], aL[mi][1], aL[mi][2], aL[mi][3], b0, b1);
            }
        }
    }

    #pragma unroll
    for (int mi = 0; mi < 2; mi++)
        #pragma unroll
        for (int ni = 0; ni < 8; ni++) {
            int r = m0 + wm + mi * 16 + gr;
            int c = n0 + wn + ni * 8 + gc * 2;
            float* cc = acc[mi][ni];
            *(float2*)&P[(size_t)r * SEQX + c] =
                make_float2(cc[0] * 0.125f, cc[1] * 0.125f);
            *(float2*)&P[(size_t)(r + 8) * SEQX + c] =
                make_float2(cc[2] * 0.125f, cc[3] * 0.125f);
        }
}

// ============================================================================
// stats + head-average: per (b,q), softmax each head row, write fp16 probs
// and fp32 head-averaged row.
// ============================================================================
__global__ __launch_bounds__(256)
void stats_avg_kernel(const float* __restrict__ P, __half* __restrict__ Ph,
                      float* __restrict__ avg)
{
    __shared__ float red[8];
    const int bq = blockIdx.x;
    const int t  = threadIdx.x;
    const int b  = bq >> 11;
    const int q  = bq & 2047;

    float avgacc[8] = {};

    for (int h = 0; h < NUM_HEADSX; ++h) {
        const int z = b * 16 + h;
        const float2* p2 = (const float2*)(P + ((size_t)z * SEQX + q) * SEQX);
        __half2* o2 = (__half2*)(Ph + ((size_t)z * SEQX + q) * SEQX);

        float2 v[4];
        float mx = -1e30f;
        #pragma unroll
        for (int i = 0; i < 4; i++) {
            v[i] = p2[t + i * 256];
            mx = fmaxf(mx, fmaxf(v[i].x, v[i].y));
        }
        #pragma unroll
        for (int o = 16; o > 0; o >>= 1)
            mx = fmaxf(mx, __shfl_xor_sync(0xffffffffu, mx, o));
        if ((t & 31) == 0) red[t >> 5] = mx;
        __syncthreads();
        float bm = red[0];
        #pragma unroll
        for (int w = 1; w < 8; w++) bm = fmaxf(bm, red[w]);
        __syncthreads();

        float s = 0.f;
        #pragma unroll
        for (int i = 0; i < 4; i++) {
            v[i].x = __expf(v[i].x - bm);
            v[i].y = __expf(v[i].y - bm);
            s += v[i].x + v[i].y;
        }
        #pragma unroll
        for (int o = 16; o > 0; o >>= 1)
            s += __shfl_xor_sync(0xffffffffu, s, o);
        if ((t & 31) == 0) red[t >> 5] = s;
        __syncthreads();
        float bs = 0.f;
        #pragma unroll
        for (int w = 0; w < 8; w++) bs += red[w];
        float inv = 1.0f / bs;

        #pragma unroll
        for (int i = 0; i < 4; i++) {
            float px = v[i].x * inv, py = v[i].y * inv;
            o2[t + i * 256] = __floats2half2_rn(px, py);
            avgacc[2 * i]     += px;
            avgacc[2 * i + 1] += py;
        }
        __syncthreads();
    }

    float2* a2 = (float2*)(avg + (size_t)bq * SEQX);
    #pragma unroll
    for (int i = 0; i < 4; i++)
        a2[t + i * 256] = make_float2(avgacc[2 * i] * (1.0f / NUM_HEADSX),
                                      avgacc[2 * i + 1] * (1.0f / NUM_HEADSX));
}

// ============================================================================
// AV: O_h = P_h(fp16 probs) @ Vt_h^T (fp16 hi/lo), fp32 acc.
// ============================================================================
__global__ __launch_bounds__(256)
void av_gemm(const __half* __restrict__ P,
             const __half* __restrict__ Vh, const __half* __restrict__ Vl,
             float* __restrict__ O)
{
    constexpr int BM = 128, BK = 64;
    constexpr int SA = 72;

    __shared__ __align__(16) __half As[BM * SA];
    __shared__ __align__(16) __half BsH[64 * SA];
    __shared__ __align__(16) __half BsL[64 * SA];

    const int z = blockIdx.z, b = z >> 4, h = z & 15;
    P  += (size_t)z * SEQX * SEQX;
    Vh += (size_t)z * D_HEADX * SEQX;
    Vl += (size_t)z * D_HEADX * SEQX;
    O  += (size_t)b * SEQX * D_MODELX + h * D_HEADX;

    const int tid  = threadIdx.x;
    const int m0   = blockIdx.y * BM;
    const int warp = tid >> 5, lane = tid & 31;
    const int wm = (warp & 3) * 32;
    const int wn = (warp >> 2) * 32;
    const int gr = lane >> 2;
    const int gc = lane & 3;

    float acc[2][4][4] = {};
    uint4 pa[4], pbh[2], pbl[2];

    {
        #pragma unroll
        for (int i = 0; i < 4; i++) {
            int idx = tid + i * 256, row = idx >> 3, c8 = idx & 7;
            pa[i] = *(const uint4*)(P + (size_t)(m0 + row) * SEQX + c8 * 8);
        }
        #pragma unroll
        for (int i = 0; i < 2; i++) {
            int idx = tid + i * 256, row = idx >> 3, c8 = idx & 7;
            pbh[i] = *(const uint4*)(Vh + (size_t)row * SEQX + c8 * 8);
            pbl[i] = *(const uint4*)(Vl + (size_t)row * SEQX + c8 * 8);
        }
    }

    const int niter = SEQX / BK;  // 32
    for (int it = 0; it < niter; ++it) {
        #pragma unroll
        for (int i = 0; i < 4; i++) {
            int idx = tid + i * 256, row = idx >> 3, c8 = idx & 7;
            *(uint4*)&As[row * SA + c8 * 8] = pa[i];
        }
        #pragma unroll
        for (int i = 0; i < 2; i++) {
            int idx = tid + i * 256, row = idx >> 3, c8 = idx & 7;
            *(uint4*)&BsH[row * SA + c8 * 8] = pbh[i];
            *(uint4*)&BsL[row * SA + c8 * 8] = pbl[i];
        }
        __syncthreads();

        if (it + 1 < niter) {
            int k0 = (it + 1) * BK;
            #pragma unroll
            for (int i = 0; i < 4; i++) {
                int idx = tid + i * 256, row = idx >> 3, c8 = idx & 7;
                pa[i] = *(const uint4*)(P + (size_t)(m0 + row) * SEQX + k0 + c8 * 8);
            }
            #pragma unroll
            for (int i = 0; i < 2; i++) {
                int idx = tid + i * 256, row = idx >> 3, c8 = idx & 7;
                pbh[i] = *(const uint4*)(Vh + (size_t)row * SEQX + k0 + c8 * 8);
                pbl[i] = *(const uint4*)(Vl + (size_t)row * SEQX + k0 + c8 * 8);
            }
        }

        #pragma unroll
        for (int ks = 0; ks < 4; ks++) {
            const int kb = ks * 16;
            unsigned a[2][4], bH[4][2], bL[4][2];
            #pragma unroll
            for (int mi = 0; mi < 2; mi++) {
                int r = (wm + mi * 16 + gr) * SA + kb + gc * 2;
                a[mi][0] = *(const unsigned*)&As[r];
                a[mi][1] = *(const unsigned*)&As[r + 8 * SA];
                a[mi][2] = *(const unsigned*)&As[r + 8];
                a[mi][3] = *(const unsigned*)&As[r + 8 * SA + 8];
            }
            #pragma unroll
            for (int ni = 0; ni < 4; ni++) {
                int r = (wn + ni * 8 + gr) * SA + kb + gc * 2;
                bH[ni][0] = *(const unsigned*)&BsH[r];
                bH[ni][1] = *(const unsigned*)&BsH[r + 8];
                bL[ni][0] = *(const unsigned*)&BsL[r];
                bL[ni][1] = *(const unsigned*)&BsL[r + 8];
            }
            #pragma unroll
            for (int mi = 0; mi < 2; mi++)
                #pragma unroll
                for (int ni = 0; ni < 4; ni++) {
                    MMA_F16(acc[mi][ni], a[mi][0], a[mi][1], a[mi][2], a[mi][3],
                            bH[ni][0], bH[ni][1]);
                    MMA_F16(acc[mi][ni], a[mi][0], a[mi][1], a[mi][2], a[mi][3],
                            bL[ni][0], bL[ni][1]);
                }
        }
        __syncthreads();
    }

    #pragma unroll
    for (int mi = 0; mi < 2; mi++)
        #pragma unroll
        for (int ni = 0; ni < 4; ni++) {
            int r = m0 + wm + mi * 16 + gr;
            int c = wn + ni * 8 + gc * 2;
            float* cc = acc[mi][ni];
            *(float2*)&O[(size_t)r * D_MODELX + c]       = make_float2(cc[0], cc[1]);
            *(float2*)&O[(size_t)(r + 8) * D_MODELX + c] = make_float2(cc[2], cc[3]);
        }
}

// ============================================================================
// launch
// ============================================================================
extern "C" void kernel_launch(void* const* d_in, const int* in_sizes, int n_in,
                              void* d_out, int out_size)
{
    const float* x_q = (const float*)d_in[0];
    const float* x_k = (const float*)d_in[1];
    const float* x_v = (const float*)d_in[2];
    const float* Wq  = (const float*)d_in[3];
    const float* bq  = (const float*)d_in[4];
    const float* Wk  = (const float*)d_in[5];
    const float* bk  = (const float*)d_in[6];
    const float* Wv  = (const float*)d_in[7];
    const float* bv  = (const float*)d_in[8];
    const float* Wo  = (const float*)d_in[9];
    const float* bo  = (const float*)d_in[10];

    float* out = (float*)d_out;
    float* avg = out + (size_t)M_TOK * D_MODELX;

    __nv_bfloat16 *Qh, *Ql, *Kh, *Kl;
    __half *Vth, *Vtl, *Ph;
    float *gO, *P;
    cudaGetSymbolAddress((void**)&Qh, g_Qh);
    cudaGetSymbolAddress((void**)&Ql, g_Ql);
    cudaGetSymbolAddress((void**)&Kh, g_Kh);
    cudaGetSymbolAddress((void**)&Kl, g_Kl);
    cudaGetSymbolAddress((void**)&Vth, g_Vth);
    cudaGetSymbolAddress((void**)&Vtl, g_Vtl);
    cudaGetSymbolAddress((void**)&gO, g_O);
    cudaGetSymbolAddress((void**)&P, g_P);
    cudaGetSymbolAddress((void**)&Ph, g_Ph);

    dim3 blk(256);
    dim3 gproj(D_MODELX / 64, M_TOK / 128, 1);   // (16, 64)

    // 1-3) projections: Q/K -> bf16 hi/lo, V -> transposed fp16 hi/lo
    mma_gemm<5><<<gproj, blk>>>(x_q, Wq, nullptr, Qh, Ql,
                                D_MODELX, D_MODELX, D_MODELX, D_MODELX, bq);
    mma_gemm<5><<<gproj, blk>>>(x_k, Wk, nullptr, Kh, Kl,
                                D_MODELX, D_MODELX, D_MODELX, D_MODELX, bk);
    mma_gemm<3><<<gproj, blk>>>(x_v, Wv, nullptr, Vth, Vtl,
                                D_MODELX, D_MODELX, 0, D_MODELX, bv);

    // 4) scores: raw P = (Q_h @ K_h^T) / 8 (pure bf16 MMA, no conversion)
    dim3 gsc(SEQX / 128, SEQX / 128, NZ);        // (16, 16, 64)
    scores_gemm<<<gsc, blk>>>(Qh, Ql, Kh, Kl, P);

    // 5) softmax stats + fp16 probs + head-average
    stats_avg_kernel<<<M_TOK, blk>>>(P, Ph, avg);

    // 6) AV fp16 MMA
    dim3 gav(1, SEQX / 128, NZ);                 // (1, 16, 64)
    av_gemm<<<gav, blk>>>(Ph, Vth, Vtl, gO);

    // 7) output projection (fp32 out)
    mma_gemm<0><<<gproj, blk>>>(gO, Wo, out, nullptr, nullptr,
                                D_MODELX, D_MODELX, D_MODELX, D_MODELX, bo);
}

// round 6
// speedup vs baseline: 1.2850x; 1.0257x over previous
#include <cuda_runtime.h>
#include <cuda_bf16.h>
#include <cuda_fp16.h>
#include <cstdint>

#define D_MODELX 1024
#define NUM_HEADSX 16
#define D_HEADX 64
#define BATCHX 4
#define SEQX 2048
#define M_TOK (BATCHX * SEQX)    // 8192
#define NZ (BATCHX * NUM_HEADSX) // 64

// ---- static device scratch ----
__device__ __nv_bfloat16 g_Qh[(size_t)M_TOK * D_MODELX];
__device__ __nv_bfloat16 g_Ql[(size_t)M_TOK * D_MODELX];
__device__ __nv_bfloat16 g_Kh[(size_t)M_TOK * D_MODELX];
__device__ __nv_bfloat16 g_Kl[(size_t)M_TOK * D_MODELX];
__device__ __half g_Vth[(size_t)M_TOK * D_MODELX];  // [Z][64][2048] fp16 hi
__device__ __half g_Vtl[(size_t)M_TOK * D_MODELX];  // [Z][64][2048] fp16 lo
__device__ float  g_O[(size_t)M_TOK * D_MODELX];
__device__ __half g_P[(size_t)NZ * SEQX * SEQX];    // 0.5 GiB raw fp16 scores
__device__ float  g_rmax[(size_t)NZ * SEQX];
__device__ float  g_rinv[(size_t)NZ * SEQX];

__device__ __forceinline__ unsigned pack_bf2(float x, float y) {
    __nv_bfloat162 t = __floats2bfloat162_rn(x, y);
    return *reinterpret_cast<unsigned*>(&t);
}

#define MMA_BF16(c, a0, a1, a2, a3, b0, b1)                                   \
    asm volatile(                                                             \
        "mma.sync.aligned.m16n8k16.row.col.f32.bf16.bf16.f32 "                \
        "{%0,%1,%2,%3},{%4,%5,%6,%7},{%8,%9},{%0,%1,%2,%3};"                  \
        : "+f"(c[0]), "+f"(c[1]), "+f"(c[2]), "+f"(c[3])                      \
        : "r"(a0), "r"(a1), "r"(a2), "r"(a3), "r"(b0), "r"(b1))

#define MMA_F16(c, a0, a1, a2, a3, b0, b1)                                    \
    asm volatile(                                                             \
        "mma.sync.aligned.m16n8k16.row.col.f32.f16.f16.f32 "                  \
        "{%0,%1,%2,%3},{%4,%5,%6,%7},{%8,%9},{%0,%1,%2,%3};"                  \
        : "+f"(c[0]), "+f"(c[1]), "+f"(c[2]), "+f"(c[3])                      \
        : "r"(a0), "r"(a1), "r"(a2), "r"(a3), "r"(b0), "r"(b1))

// ============================================================================
// NT bf16-split MMA GEMM (fp32 in, split in-kernel): C = A @ B^T + bias
// MODE 0: fp32 out + bias (output projection)
// MODE 3: V projection, transposed fp16 hi/lo store into [Z][64][2048]
// MODE 5: Q/K projection, bf16 hi/lo out + bias
// Block tile 128x64x32, 256 threads (8 warps 4x2), warp tile 32x32.
// ============================================================================
template <int MODE>
__global__ __launch_bounds__(256)
void mma_gemm(const float* __restrict__ A,
              const float* __restrict__ B,
              float* __restrict__ C,
              void* __restrict__ Chv, void* __restrict__ Clv,
              int lda, int ldb, int ldc,
              int K, const float* __restrict__ bias)
{
    constexpr int BM = 128, BN = 64, BK = 32;
    constexpr int SA = 40;

    __shared__ __align__(16) __nv_bfloat16 AsH[BM * SA];
    __shared__ __align__(16) __nv_bfloat16 AsL[BM * SA];
    __shared__ __align__(16) __nv_bfloat16 BsH[BN * SA];
    __shared__ __align__(16) __nv_bfloat16 BsL[BN * SA];

    const int tid  = threadIdx.x;
    const int m0   = blockIdx.y * BM;
    const int n0   = blockIdx.x * BN;
    const int warp = tid >> 5, lane = tid & 31;
    const int wm = (warp & 3) * 32;
    const int wn = (warp >> 2) * 32;
    const int gr = lane >> 2;
    const int gc = lane & 3;

    float acc[2][4][4] = {};
    float4 ra[4], rb[2];

    {
        #pragma unroll
        for (int i = 0; i < 4; i++) {
            int idx = tid + i * 256, row = idx >> 3, c4 = idx & 7;
            ra[i] = *(const float4*)(A + (size_t)(m0 + row) * lda + c4 * 4);
        }
        #pragma unroll
        for (int i = 0; i < 2; i++) {
            int idx = tid + i * 256, row = idx >> 3, c4 = idx & 7;
            rb[i] = *(const float4*)(B + (size_t)(n0 + row) * ldb + c4 * 4);
        }
    }

    const int niter = K / BK;
    for (int it = 0; it < niter; ++it) {
        #pragma unroll
        for (int i = 0; i < 4; i++) {
            int idx = tid + i * 256, row = idx >> 3, c4 = idx & 7;
            float v0 = ra[i].x, v1 = ra[i].y, v2 = ra[i].z, v3 = ra[i].w;
            float h0 = __bfloat162float(__float2bfloat16_rn(v0));
            float h1 = __bfloat162float(__float2bfloat16_rn(v1));
            float h2 = __bfloat162float(__float2bfloat16_rn(v2));
            float h3 = __bfloat162float(__float2bfloat16_rn(v3));
            uint2 H, L;
            H.x = pack_bf2(v0, v1); H.y = pack_bf2(v2, v3);
            L.x = pack_bf2(v0 - h0, v1 - h1); L.y = pack_bf2(v2 - h2, v3 - h3);
            *(uint2*)&AsH[row * SA + c4 * 4] = H;
            *(uint2*)&AsL[row * SA + c4 * 4] = L;
        }
        #pragma unroll
        for (int i = 0; i < 2; i++) {
            int idx = tid + i * 256, row = idx >> 3, c4 = idx & 7;
            float v0 = rb[i].x, v1 = rb[i].y, v2 = rb[i].z, v3 = rb[i].w;
            float h0 = __bfloat162float(__float2bfloat16_rn(v0));
            float h1 = __bfloat162float(__float2bfloat16_rn(v1));
            float h2 = __bfloat162float(__float2bfloat16_rn(v2));
            float h3 = __bfloat162float(__float2bfloat16_rn(v3));
            uint2 H, L;
            H.x = pack_bf2(v0, v1); H.y = pack_bf2(v2, v3);
            L.x = pack_bf2(v0 - h0, v1 - h1); L.y = pack_bf2(v2 - h2, v3 - h3);
            *(uint2*)&BsH[row * SA + c4 * 4] = H;
            *(uint2*)&BsL[row * SA + c4 * 4] = L;
        }
        __syncthreads();

        if (it + 1 < niter) {
            int k0 = (it + 1) * BK;
            #pragma unroll
            for (int i = 0; i < 4; i++) {
                int idx = tid + i * 256, row = idx >> 3, c4 = idx & 7;
                ra[i] = *(const float4*)(A + (size_t)(m0 + row) * lda + k0 + c4 * 4);
            }
            #pragma unroll
            for (int i = 0; i < 2; i++) {
                int idx = tid + i * 256, row = idx >> 3, c4 = idx & 7;
                rb[i] = *(const float4*)(B + (size_t)(n0 + row) * ldb + k0 + c4 * 4);
            }
        }

        #pragma unroll
        for (int ks = 0; ks < 2; ks++) {
            const int kb = ks * 16;
            unsigned aH[2][4], aL[2][4], bH[4][2], bL[4][2];
            #pragma unroll
            for (int mi = 0; mi < 2; mi++) {
                int r = (wm + mi * 16 + gr) * SA + kb + gc * 2;
                aH[mi][0] = *(const unsigned*)&AsH[r];
                aH[mi][1] = *(const unsigned*)&AsH[r + 8 * SA];
                aH[mi][2] = *(const unsigned*)&AsH[r + 8];
                aH[mi][3] = *(const unsigned*)&AsH[r + 8 * SA + 8];
                aL[mi][0] = *(const unsigned*)&AsL[r];
                aL[mi][1] = *(const unsigned*)&AsL[r + 8 * SA];
                aL[mi][2] = *(const unsigned*)&AsL[r + 8];
                aL[mi][3] = *(const unsigned*)&AsL[r + 8 * SA + 8];
            }
            #pragma unroll
            for (int ni = 0; ni < 4; ni++) {
                int r = (wn + ni * 8 + gr) * SA + kb + gc * 2;
                bH[ni][0] = *(const unsigned*)&BsH[r];
                bH[ni][1] = *(const unsigned*)&BsH[r + 8];
                bL[ni][0] = *(const unsigned*)&BsL[r];
                bL[ni][1] = *(const unsigned*)&BsL[r + 8];
            }
            #pragma unroll
            for (int mi = 0; mi < 2; mi++)
                #pragma unroll
                for (int ni = 0; ni < 4; ni++) {
                    MMA_BF16(acc[mi][ni], aH[mi][0], aH[mi][1], aH[mi][2], aH[mi][3],
                             bH[ni][0], bH[ni][1]);
                    MMA_BF16(acc[mi][ni], aH[mi][0], aH[mi][1], aH[mi][2], aH[mi][3],
                             bL[ni][0], bL[ni][1]);
                    MMA_BF16(acc[mi][ni], aL[mi][0], aL[mi][1], aL[mi][2], aL[mi][3],
                             bH[ni][0], bH[ni][1]);
                }
        }
        __syncthreads();
    }

    #pragma unroll
    for (int mi = 0; mi < 2; mi++)
        #pragma unroll
        for (int ni = 0; ni < 4; ni++) {
            int r = m0 + wm + mi * 16 + gr;
            int c = n0 + wn + ni * 8 + gc * 2;
            float* cc = acc[mi][ni];
            if (MODE == 3) {
                __half* Ch = (__half*)Chv;
                __half* Cl = (__half*)Clv;
                int b = r >> 11, s = r & 2047;
                int h = c >> 6, d = c & 63;
                float b0 = bias[c], b1 = bias[c + 1];
                float v00 = cc[0] + b0, v01 = cc[1] + b1;
                float v10 = cc[2] + b0, v11 = cc[3] + b1;
                size_t base = ((size_t)(b * 16 + h) * 64 + d) * 2048;
                __half h00 = __float2half_rn(v00);
                __half h01 = __float2half_rn(v01);
                __half h10 = __float2half_rn(v10);
                __half h11 = __float2half_rn(v11);
                Ch[base + s]            = h00;
                Ch[base + 2048 + s]     = h01;
                Ch[base + s + 8]        = h10;
                Ch[base + 2048 + s + 8] = h11;
                Cl[base + s]            = __float2half_rn(v00 - __half2float(h00));
                Cl[base + 2048 + s]     = __float2half_rn(v01 - __half2float(h01));
                Cl[base + s + 8]        = __float2half_rn(v10 - __half2float(h10));
                Cl[base + 2048 + s + 8] = __float2half_rn(v11 - __half2float(h11));
            } else if (MODE == 5) {
                __nv_bfloat16* Ch = (__nv_bfloat16*)Chv;
                __nv_bfloat16* Cl = (__nv_bfloat16*)Clv;
                float b0 = bias[c], b1 = bias[c + 1];
                float v00 = cc[0] + b0, v01 = cc[1] + b1;
                float v10 = cc[2] + b0, v11 = cc[3] + b1;
                float h00 = __bfloat162float(__float2bfloat16_rn(v00));
                float h01 = __bfloat162float(__float2bfloat16_rn(v01));
                float h10 = __bfloat162float(__float2bfloat16_rn(v10));
                float h11 = __bfloat162float(__float2bfloat16_rn(v11));
                size_t o0 = (size_t)r * ldc + c;
                size_t o1 = (size_t)(r + 8) * ldc + c;
                *(unsigned*)&Ch[o0] = pack_bf2(v00, v01);
                *(unsigned*)&Ch[o1] = pack_bf2(v10, v11);
                *(unsigned*)&Cl[o0] = pack_bf2(v00 - h00, v01 - h01);
                *(unsigned*)&Cl[o1] = pack_bf2(v10 - h10, v11 - h11);
            } else {
                float b0 = 0.f, b1 = 0.f;
                if (bias) { b0 = bias[c]; b1 = bias[c + 1]; }
                float2 v0 = make_float2(cc[0] + b0, cc[1] + b1);
                float2 v1 = make_float2(cc[2] + b0, cc[3] + b1);
                *(float2*)&C[(size_t)r * ldc + c]       = v0;
                *(float2*)&C[(size_t)(r + 8) * ldc + c] = v1;
            }
        }
}

// ============================================================================
// Scores: P[z] = fp16((Q_h @ K_h^T)/8), pre-split bf16. K=64, single smem
// load, no k-loop. Block tile 128x128, 8 warps (4M x 2N), warp tile 32x64.
// ============================================================================
__global__ __launch_bounds__(256)
void scores_gemm(const __nv_bfloat16* __restrict__ Qh, const __nv_bfloat16* __restrict__ Ql,
                 const __nv_bfloat16* __restrict__ Kh, const __nv_bfloat16* __restrict__ Kl,
                 __half* __restrict__ P)
{
    constexpr int SA = 72;
    __shared__ __align__(16) __nv_bfloat16 AsH[128 * SA];
    __shared__ __align__(16) __nv_bfloat16 AsL[128 * SA];
    __shared__ __align__(16) __nv_bfloat16 BsH[128 * SA];
    __shared__ __align__(16) __nv_bfloat16 BsL[128 * SA];

    const int z = blockIdx.z, b = z >> 4, h = z & 15;
    const size_t qo = (size_t)b * SEQX * D_MODELX + h * D_HEADX;
    Qh += qo; Ql += qo; Kh += qo; Kl += qo;
    P += (size_t)z * SEQX * SEQX;

    const int tid  = threadIdx.x;
    const int m0   = blockIdx.y * 128;
    const int n0   = blockIdx.x * 128;
    const int warp = tid >> 5, lane = tid & 31;
    const int wm = (warp & 3) * 32;
    const int wn = (warp >> 2) * 64;
    const int gr = lane >> 2;
    const int gc = lane & 3;

    #pragma unroll
    for (int i = 0; i < 4; i++) {
        int idx = tid + i * 256, row = idx >> 3, c8 = idx & 7;
        size_t oa = (size_t)(m0 + row) * D_MODELX + c8 * 8;
        size_t ob = (size_t)(n0 + row) * D_MODELX + c8 * 8;
        *(uint4*)&AsH[row * SA + c8 * 8] = *(const uint4*)(Qh + oa);
        *(uint4*)&AsL[row * SA + c8 * 8] = *(const uint4*)(Ql + oa);
        *(uint4*)&BsH[row * SA + c8 * 8] = *(const uint4*)(Kh + ob);
        *(uint4*)&BsL[row * SA + c8 * 8] = *(const uint4*)(Kl + ob);
    }
    __syncthreads();

    float acc[2][8][4] = {};

    #pragma unroll
    for (int ks = 0; ks < 4; ks++) {
        const int kb = ks * 16;
        unsigned aH[2][4], aL[2][4];
        #pragma unroll
        for (int mi = 0; mi < 2; mi++) {
            int r = (wm + mi * 16 + gr) * SA + kb + gc * 2;
            aH[mi][0] = *(const unsigned*)&AsH[r];
            aH[mi][1] = *(const unsigned*)&AsH[r + 8 * SA];
            aH[mi][2] = *(const unsigned*)&AsH[r + 8];
            aH[mi][3] = *(const unsigned*)&AsH[r + 8 * SA + 8];
            aL[mi][0] = *(const unsigned*)&AsL[r];
            aL[mi][1] = *(const unsigned*)&AsL[r + 8 * SA];
            aL[mi][2] = *(const unsigned*)&AsL[r + 8];
            aL[mi][3] = *(const unsigned*)&AsL[r + 8 * SA + 8];
        }
        #pragma unroll
        for (int ni = 0; ni < 8; ni++) {
            int r = (wn + ni * 8 + gr) * SA + kb + gc * 2;
            unsigned b0 = *(const unsigned*)&BsH[r];
            unsigned b1 = *(const unsigned*)&BsH[r + 8];
            unsigned l0 = *(const unsigned*)&BsL[r];
            unsigned l1 = *(const unsigned*)&BsL[r + 8];
            #pragma unroll
            for (int mi = 0; mi < 2; mi++) {
                MMA_BF16(acc[mi][ni], aH[mi][0], aH[mi][1], aH[mi][2], aH[mi][3], b0, b1);
                MMA_BF16(acc[mi][ni], aH[mi][0], aH[mi][1], aH[mi][2], aH[mi][3], l0, l1);
                MMA_BF16(acc[mi][ni], aL[mi][0], aL[mi][1], aL[mi][2], aL[mi][3], b0, b1);
            }
        }
    }

    #pragma unroll
    for (int mi = 0; mi < 2; mi++)
        #pragma unroll
        for (int ni = 0; ni < 8; ni++) {
            int r = m0 + wm + mi * 16 + gr;
            int c = n0 + wn + ni * 8 + gc * 2;
            float* cc = acc[mi][ni];
            *(__half2*)&P[(size_t)r * SEQX + c] =
                __floats2half2_rn(cc[0] * 0.125f, cc[1] * 0.125f);
            *(__half2*)&P[(size_t)(r + 8) * SEQX + c] =
                __floats2half2_rn(cc[2] * 0.125f, cc[3] * 0.125f);
        }
}

// ============================================================================
// stats + head-average: per (b,q), softmax stats for each head row from fp16
// raw scores; write rmax/rinv (tiny) and fp32 head-averaged row. No P rewrite.
// ============================================================================
__global__ __launch_bounds__(256)
void stats_avg_kernel(const __half* __restrict__ P, float* __restrict__ avg,
                      float* __restrict__ rmax, float* __restrict__ rinv)
{
    __shared__ float red[8];
    const int bq = blockIdx.x;
    const int t  = threadIdx.x;
    const int b  = bq >> 11;
    const int q  = bq & 2047;

    float avgacc[8] = {};

    for (int h = 0; h < NUM_HEADSX; ++h) {
        const int z = b * 16 + h;
        const __half2* p2 = (const __half2*)(P + ((size_t)z * SEQX + q) * SEQX);

        float2 v[4];
        float mx = -1e30f;
        #pragma unroll
        for (int i = 0; i < 4; i++) {
            v[i] = __half22float2(p2[t + i * 256]);
            mx = fmaxf(mx, fmaxf(v[i].x, v[i].y));
        }
        #pragma unroll
        for (int o = 16; o > 0; o >>= 1)
            mx = fmaxf(mx, __shfl_xor_sync(0xffffffffu, mx, o));
        if ((t & 31) == 0) red[t >> 5] = mx;
        __syncthreads();
        float bm = red[0];
        #pragma unroll
        for (int w = 1; w < 8; w++) bm = fmaxf(bm, red[w]);
        __syncthreads();

        float s = 0.f;
        #pragma unroll
        for (int i = 0; i < 4; i++) {
            v[i].x = __expf(v[i].x - bm);
            v[i].y = __expf(v[i].y - bm);
            s += v[i].x + v[i].y;
        }
        #pragma unroll
        for (int o = 16; o > 0; o >>= 1)
            s += __shfl_xor_sync(0xffffffffu, s, o);
        if ((t & 31) == 0) red[t >> 5] = s;
        __syncthreads();
        float bs = 0.f;
        #pragma unroll
        for (int w = 0; w < 8; w++) bs += red[w];
        float inv = 1.0f / bs;
        if (t == 0) {
            rmax[(size_t)z * SEQX + q] = bm;
            rinv[(size_t)z * SEQX + q] = inv;
        }

        #pragma unroll
        for (int i = 0; i < 4; i++) {
            avgacc[2 * i]     += v[i].x * inv;
            avgacc[2 * i + 1] += v[i].y * inv;
        }
        __syncthreads();
    }

    float2* a2 = (float2*)(avg + (size_t)bq * SEQX);
    #pragma unroll
    for (int i = 0; i < 4; i++)
        a2[t + i * 256] = make_float2(avgacc[2 * i] * (1.0f / NUM_HEADSX),
                                      avgacc[2 * i + 1] * (1.0f / NUM_HEADSX));
}

// ============================================================================
// AV: O_h = softmax(P)[z] @ Vt_h^T. P is raw fp16 scores; exp(s-m)*inv applied
// while staging the A tile. V fp16 hi/lo, fp32 acc.
// ============================================================================
__global__ __launch_bounds__(256)
void av_gemm(const __half* __restrict__ P,
             const __half* __restrict__ Vh, const __half* __restrict__ Vl,
             const float* __restrict__ rmax, const float* __restrict__ rinv,
             float* __restrict__ O)
{
    constexpr int BM = 128, BK = 64;
    constexpr int SA = 72;

    __shared__ __align__(16) __half As[BM * SA];
    __shared__ __align__(16) __half BsH[64 * SA];
    __shared__ __align__(16) __half BsL[64 * SA];
    __shared__ float sm_m[BM], sm_i[BM];

    const int z = blockIdx.z, b = z >> 4, h = z & 15;
    P  += (size_t)z * SEQX * SEQX;
    Vh += (size_t)z * D_HEADX * SEQX;
    Vl += (size_t)z * D_HEADX * SEQX;
    O  += (size_t)b * SEQX * D_MODELX + h * D_HEADX;
    rmax += (size_t)z * SEQX;
    rinv += (size_t)z * SEQX;

    const int tid  = threadIdx.x;
    const int m0   = blockIdx.y * BM;
    const int warp = tid >> 5, lane = tid & 31;
    const int wm = (warp & 3) * 32;
    const int wn = (warp >> 2) * 32;
    const int gr = lane >> 2;
    const int gc = lane & 3;

    if (tid < BM) { sm_m[tid] = rmax[m0 + tid]; sm_i[tid] = rinv[m0 + tid]; }
    __syncthreads();

    float acc[2][4][4] = {};
    uint4 pa[4], pbh[2], pbl[2];

    {
        #pragma unroll
        for (int i = 0; i < 4; i++) {
            int idx = tid + i * 256, row = idx >> 3, c8 = idx & 7;
            pa[i] = *(const uint4*)(P + (size_t)(m0 + row) * SEQX + c8 * 8);
        }
        #pragma unroll
        for (int i = 0; i < 2; i++) {
            int idx = tid + i * 256, row = idx >> 3, c8 = idx & 7;
            pbh[i] = *(const uint4*)(Vh + (size_t)row * SEQX + c8 * 8);
            pbl[i] = *(const uint4*)(Vl + (size_t)row * SEQX + c8 * 8);
        }
    }

    const int niter = SEQX / BK;  // 32
    for (int it = 0; it < niter; ++it) {
        #pragma unroll
        for (int i = 0; i < 4; i++) {
            int idx = tid + i * 256, row = idx >> 3, c8 = idx & 7;
            float m = sm_m[row], inv = sm_i[row];
            const __half2* hp = (const __half2*)&pa[i];
            uint4 out;
            unsigned* op = (unsigned*)&out;
            #pragma unroll
            for (int j = 0; j < 4; j++) {
                float2 f = __half22float2(hp[j]);
                __half2 e = __floats2half2_rn(__expf(f.x - m) * inv,
                                              __expf(f.y - m) * inv);
                op[j] = *(unsigned*)&e;
            }
            *(uint4*)&As[row * SA + c8 * 8] = out;
        }
        #pragma unroll
        for (int i = 0; i < 2; i++) {
            int idx = tid + i * 256, row = idx >> 3, c8 = idx & 7;
            *(uint4*)&BsH[row * SA + c8 * 8] = pbh[i];
            *(uint4*)&BsL[row * SA + c8 * 8] = pbl[i];
        }
        __syncthreads();

        if (it + 1 < niter) {
            int k0 = (it + 1) * BK;
            #pragma unroll
            for (int i = 0; i < 4; i++) {
                int idx = tid + i * 256, row = idx >> 3, c8 = idx & 7;
                pa[i] = *(const uint4*)(P + (size_t)(m0 + row) * SEQX + k0 + c8 * 8);
            }
            #pragma unroll
            for (int i = 0; i < 2; i++) {
                int idx = tid + i * 256, row = idx >> 3, c8 = idx & 7;
                pbh[i] = *(const uint4*)(Vh + (size_t)row * SEQX + k0 + c8 * 8);
                pbl[i] = *(const uint4*)(Vl + (size_t)row * SEQX + k0 + c8 * 8);
            }
        }

        #pragma unroll
        for (int ks = 0; ks < 4; ks++) {
            const int kb = ks * 16;
            unsigned a[2][4], bH[4][2], bL[4][2];
            #pragma unroll
            for (int mi = 0; mi < 2; mi++) {
                int r = (wm + mi * 16 + gr) * SA + kb + gc * 2;
                a[mi][0] = *(const unsigned*)&As[r];
                a[mi][1] = *(const unsigned*)&As[r + 8 * SA];
                a[mi][2] = *(const unsigned*)&As[r + 8];
                a[mi][3] = *(const unsigned*)&As[r + 8 * SA + 8];
            }
            #pragma unroll
            for (int ni = 0; ni < 4; ni++) {
                int r = (wn + ni * 8 + gr) * SA + kb + gc * 2;
                bH[ni][0] = *(const unsigned*)&BsH[r];
                bH[ni][1] = *(const unsigned*)&BsH[r + 8];
                bL[ni][0] = *(const unsigned*)&BsL[r];
                bL[ni][1] = *(const unsigned*)&BsL[r + 8];
            }
            #pragma unroll
            for (int mi = 0; mi < 2; mi++)
                #pragma unroll
                for (int ni = 0; ni < 4; ni++) {
                    MMA_F16(acc[mi][ni], a[mi][0], a[mi][1], a[mi][2], a[mi][3],
                            bH[ni][0], bH[ni][1]);
                    MMA_F16(acc[mi][ni], a[mi][0], a[mi][1], a[mi][2], a[mi][3],
                            bL[ni][0], bL[ni][1]);
                }
        }
        __syncthreads();
    }

    #pragma unroll
    for (int mi = 0; mi < 2; mi++)
        #pragma unroll
        for (int ni = 0; ni < 4; ni++) {
            int r = m0 + wm + mi * 16 + gr;
            int c = wn + ni * 8 + gc * 2;
            float* cc = acc[mi][ni];
            *(float2*)&O[(size_t)r * D_MODELX + c]       = make_float2(cc[0], cc[1]);
            *(float2*)&O[(size_t)(r + 8) * D_MODELX + c] = make_float2(cc[2], cc[3]);
        }
}

// ============================================================================
// launch
// ============================================================================
extern "C" void kernel_launch(void* const* d_in, const int* in_sizes, int n_in,
                              void* d_out, int out_size)
{
    const float* x_q = (const float*)d_in[0];
    const float* x_k = (const float*)d_in[1];
    const float* x_v = (const float*)d_in[2];
    const float* Wq  = (const float*)d_in[3];
    const float* bq  = (const float*)d_in[4];
    const float* Wk  = (const float*)d_in[5];
    const float* bk  = (const float*)d_in[6];
    const float* Wv  = (const float*)d_in[7];
    const float* bv  = (const float*)d_in[8];
    const float* Wo  = (const float*)d_in[9];
    const float* bo  = (const float*)d_in[10];

    float* out = (float*)d_out;
    float* avg = out + (size_t)M_TOK * D_MODELX;

    __nv_bfloat16 *Qh, *Ql, *Kh, *Kl;
    __half *Vth, *Vtl, *P;
    float *gO, *rmax, *rinv;
    cudaGetSymbolAddress((void**)&Qh, g_Qh);
    cudaGetSymbolAddress((void**)&Ql, g_Ql);
    cudaGetSymbolAddress((void**)&Kh, g_Kh);
    cudaGetSymbolAddress((void**)&Kl, g_Kl);
    cudaGetSymbolAddress((void**)&Vth, g_Vth);
    cudaGetSymbolAddress((void**)&Vtl, g_Vtl);
    cudaGetSymbolAddress((void**)&gO, g_O);
    cudaGetSymbolAddress((void**)&P, g_P);
    cudaGetSymbolAddress((void**)&rmax, g_rmax);
    cudaGetSymbolAddress((void**)&rinv, g_rinv);

    dim3 blk(256);
    dim3 gproj(D_MODELX / 64, M_TOK / 128, 1);   // (16, 64)

    // 1-3) projections: Q/K -> bf16 hi/lo, V -> transposed fp16 hi/lo
    mma_gemm<5><<<gproj, blk>>>(x_q, Wq, nullptr, Qh, Ql,
                                D_MODELX, D_MODELX, D_MODELX, D_MODELX, bq);
    mma_gemm<5><<<gproj, blk>>>(x_k, Wk, nullptr, Kh, Kl,
                                D_MODELX, D_MODELX, D_MODELX, D_MODELX, bk);
    mma_gemm<3><<<gproj, blk>>>(x_v, Wv, nullptr, Vth, Vtl,
                                D_MODELX, D_MODELX, 0, D_MODELX, bv);

    // 4) scores: raw fp16 P = (Q_h @ K_h^T) / 8
    dim3 gsc(SEQX / 128, SEQX / 128, NZ);        // (16, 16, 64)
    scores_gemm<<<gsc, blk>>>(Qh, Ql, Kh, Kl, P);

    // 5) softmax stats + head-average (no P rewrite)
    stats_avg_kernel<<<M_TOK, blk>>>(P, avg, rmax, rinv);

    // 6) AV fp16 MMA with on-the-fly exp
    dim3 gav(1, SEQX / 128, NZ);                 // (1, 16, 64)
    av_gemm<<<gav, blk>>>(P, Vth, Vtl, rmax, rinv, gO);

    // 7) output projection (fp32 out)
    mma_gemm<0><<<gproj, blk>>>(gO, Wo, out, nullptr, nullptr,
                                D_MODELX, D_MODELX, D_MODELX, D_MODELX, bo);
}

// round 7
// speedup vs baseline: 1.4353x; 1.1170x over previous
#include <cuda_runtime.h>
#include <cuda_bf16.h>
#include <cuda_fp16.h>
#include <cstdint>

#define D_MODELX 1024
#define NUM_HEADSX 16
#define D_HEADX 64
#define BATCHX 4
#define SEQX 2048
#define M_TOK (BATCHX * SEQX)    // 8192
#define NZ (BATCHX * NUM_HEADSX) // 64

// ---- static device scratch ----
__device__ __nv_bfloat16 g_Qh[(size_t)M_TOK * D_MODELX];
__device__ __nv_bfloat16 g_Ql[(size_t)M_TOK * D_MODELX];
__device__ __nv_bfloat16 g_Kh[(size_t)M_TOK * D_MODELX];
__device__ __nv_bfloat16 g_Kl[(size_t)M_TOK * D_MODELX];
__device__ __half g_Vth[(size_t)M_TOK * D_MODELX];  // [Z][64][2048] fp16 hi
__device__ __half g_Vtl[(size_t)M_TOK * D_MODELX];  // [Z][64][2048] fp16 lo
__device__ float  g_O[(size_t)M_TOK * D_MODELX];
__device__ __half g_P[(size_t)NZ * SEQX * SEQX];    // 0.5 GiB raw fp16 scores
__device__ float  g_rmax[(size_t)NZ * SEQX];
__device__ float  g_rinv[(size_t)NZ * SEQX];

__device__ __forceinline__ unsigned pack_bf2(float x, float y) {
    __nv_bfloat162 t = __floats2bfloat162_rn(x, y);
    return *reinterpret_cast<unsigned*>(&t);
}

__device__ __forceinline__ unsigned smem_u32(const void* p) {
    return (unsigned)__cvta_generic_to_shared(p);
}

#define LDSM_X4(r0, r1, r2, r3, addr)                                         \
    asm volatile("ldmatrix.sync.aligned.m8n8.x4.shared.b16 {%0,%1,%2,%3}, [%4];" \
        : "=r"(r0), "=r"(r1), "=r"(r2), "=r"(r3) : "r"(addr))

#define MMA_BF16(c, a0, a1, a2, a3, b0, b1)                                   \
    asm volatile(                                                             \
        "mma.sync.aligned.m16n8k16.row.col.f32.bf16.bf16.f32 "                \
        "{%0,%1,%2,%3},{%4,%5,%6,%7},{%8,%9},{%0,%1,%2,%3};"                  \
        : "+f"(c[0]), "+f"(c[1]), "+f"(c[2]), "+f"(c[3])                      \
        : "r"(a0), "r"(a1), "r"(a2), "r"(a3), "r"(b0), "r"(b1))

#define MMA_F16(c, a0, a1, a2, a3, b0, b1)                                    \
    asm volatile(                                                             \
        "mma.sync.aligned.m16n8k16.row.col.f32.f16.f16.f32 "                  \
        "{%0,%1,%2,%3},{%4,%5,%6,%7},{%8,%9},{%0,%1,%2,%3};"                  \
        : "+f"(c[0]), "+f"(c[1]), "+f"(c[2]), "+f"(c[3])                      \
        : "r"(a0), "r"(a1), "r"(a2), "r"(a3), "r"(b0), "r"(b1))

// ============================================================================
// NT bf16-split MMA GEMM (fp32 in, split in-kernel): C = A @ B^T + bias
// MODE 0: fp32 out + bias (output projection)
// MODE 3: V projection, transposed fp16 hi/lo store into [Z][64][2048]
// MODE 5: Q/K projection, bf16 hi/lo out + bias
// Block tile 128x64x32, 256 threads (8 warps 4x2), warp tile 32x32.
// Fragments via ldmatrix.
// ============================================================================
template <int MODE>
__global__ __launch_bounds__(256)
void mma_gemm(const float* __restrict__ A,
              const float* __restrict__ B,
              float* __restrict__ C,
              void* __restrict__ Chv, void* __restrict__ Clv,
              int lda, int ldb, int ldc,
              int K, const float* __restrict__ bias)
{
    constexpr int BM = 128, BN = 64, BK = 32;
    constexpr int SA = 40;

    __shared__ __align__(16) __nv_bfloat16 AsH[BM * SA];
    __shared__ __align__(16) __nv_bfloat16 AsL[BM * SA];
    __shared__ __align__(16) __nv_bfloat16 BsH[BN * SA];
    __shared__ __align__(16) __nv_bfloat16 BsL[BN * SA];

    const int tid  = threadIdx.x;
    const int m0   = blockIdx.y * BM;
    const int n0   = blockIdx.x * BN;
    const int warp = tid >> 5, lane = tid & 31;
    const int wm = (warp & 3) * 32;
    const int wn = (warp >> 2) * 32;
    const int gr = lane >> 2;
    const int gc = lane & 3;
    const int ti = lane >> 3, ri = lane & 7;

    // ldmatrix base addresses (A: x4 tiles m{0,8}+k{0,8}; B: x4 = two n-groups x k{0,8})
    unsigned aHb[2], aLb[2], bHb[2], bLb[2];
    #pragma unroll
    for (int mi = 0; mi < 2; mi++) {
        int row = wm + mi * 16 + (ti & 1) * 8 + ri;
        int col = (ti >> 1) * 8;
        aHb[mi] = smem_u32(&AsH[row * SA + col]);
        aLb[mi] = smem_u32(&AsL[row * SA + col]);
    }
    #pragma unroll
    for (int nip = 0; nip < 2; nip++) {
        int row = wn + (nip * 2 + (ti >> 1)) * 8 + ri;
        int col = (ti & 1) * 8;
        bHb[nip] = smem_u32(&BsH[row * SA + col]);
        bLb[nip] = smem_u32(&BsL[row * SA + col]);
    }

    float acc[2][4][4] = {};
    float4 ra[4], rb[2];

    {
        #pragma unroll
        for (int i = 0; i < 4; i++) {
            int idx = tid + i * 256, row = idx >> 3, c4 = idx & 7;
            ra[i] = *(const float4*)(A + (size_t)(m0 + row) * lda + c4 * 4);
        }
        #pragma unroll
        for (int i = 0; i < 2; i++) {
            int idx = tid + i * 256, row = idx >> 3, c4 = idx & 7;
            rb[i] = *(const float4*)(B + (size_t)(n0 + row) * ldb + c4 * 4);
        }
    }

    const int niter = K / BK;
    for (int it = 0; it < niter; ++it) {
        #pragma unroll
        for (int i = 0; i < 4; i++) {
            int idx = tid + i * 256, row = idx >> 3, c4 = idx & 7;
            float v0 = ra[i].x, v1 = ra[i].y, v2 = ra[i].z, v3 = ra[i].w;
            float h0 = __bfloat162float(__float2bfloat16_rn(v0));
            float h1 = __bfloat162float(__float2bfloat16_rn(v1));
            float h2 = __bfloat162float(__float2bfloat16_rn(v2));
            float h3 = __bfloat162float(__float2bfloat16_rn(v3));
            uint2 H, L;
            H.x = pack_bf2(v0, v1); H.y = pack_bf2(v2, v3);
            L.x = pack_bf2(v0 - h0, v1 - h1); L.y = pack_bf2(v2 - h2, v3 - h3);
            *(uint2*)&AsH[row * SA + c4 * 4] = H;
            *(uint2*)&AsL[row * SA + c4 * 4] = L;
        }
        #pragma unroll
        for (int i = 0; i < 2; i++) {
            int idx = tid + i * 256, row = idx >> 3, c4 = idx & 7;
            float v0 = rb[i].x, v1 = rb[i].y, v2 = rb[i].z, v3 = rb[i].w;
            float h0 = __bfloat162float(__float2bfloat16_rn(v0));
            float h1 = __bfloat162float(__float2bfloat16_rn(v1));
            float h2 = __bfloat162float(__float2bfloat16_rn(v2));
            float h3 = __bfloat162float(__float2bfloat16_rn(v3));
            uint2 H, L;
            H.x = pack_bf2(v0, v1); H.y = pack_bf2(v2, v3);
            L.x = pack_bf2(v0 - h0, v1 - h1); L.y = pack_bf2(v2 - h2, v3 - h3);
            *(uint2*)&BsH[row * SA + c4 * 4] = H;
            *(uint2*)&BsL[row * SA + c4 * 4] = L;
        }
        __syncthreads();

        if (it + 1 < niter) {
            int k0 = (it + 1) * BK;
            #pragma unroll
            for (int i = 0; i < 4; i++) {
                int idx = tid + i * 256, row = idx >> 3, c4 = idx & 7;
                ra[i] = *(const float4*)(A + (size_t)(m0 + row) * lda + k0 + c4 * 4);
            }
            #pragma unroll
            for (int i = 0; i < 2; i++) {
                int idx = tid + i * 256, row = idx >> 3, c4 = idx & 7;
                rb[i] = *(const float4*)(B + (size_t)(n0 + row) * ldb + k0 + c4 * 4);
            }
        }

        #pragma unroll
        for (int ks = 0; ks < 2; ks++) {
            const int kb2 = ks * 32;   // 16 halves * 2 bytes
            unsigned aH[2][4], aL[2][4], bH[2][4], bL[2][4];
            #pragma unroll
            for (int mi = 0; mi < 2; mi++) {
                LDSM_X4(aH[mi][0], aH[mi][1], aH[mi][2], aH[mi][3], aHb[mi] + kb2);
                LDSM_X4(aL[mi][0], aL[mi][1], aL[mi][2], aL[mi][3], aLb[mi] + kb2);
            }
            #pragma unroll
            for (int nip = 0; nip < 2; nip++) {
                LDSM_X4(bH[nip][0], bH[nip][1], bH[nip][2], bH[nip][3], bHb[nip] + kb2);
                LDSM_X4(bL[nip][0], bL[nip][1], bL[nip][2], bL[nip][3], bLb[nip] + kb2);
            }
            #pragma unroll
            for (int mi = 0; mi < 2; mi++)
                #pragma unroll
                for (int nip = 0; nip < 2; nip++)
                    #pragma unroll
                    for (int hh = 0; hh < 2; hh++) {
                        int ni = nip * 2 + hh;
                        unsigned b0 = bH[nip][hh * 2], b1 = bH[nip][hh * 2 + 1];
                        unsigned l0 = bL[nip][hh * 2], l1 = bL[nip][hh * 2 + 1];
                        MMA_BF16(acc[mi][ni], aH[mi][0], aH[mi][1], aH[mi][2], aH[mi][3], b0, b1);
                        MMA_BF16(acc[mi][ni], aH[mi][0], aH[mi][1], aH[mi][2], aH[mi][3], l0, l1);
                        MMA_BF16(acc[mi][ni], aL[mi][0], aL[mi][1], aL[mi][2], aL[mi][3], b0, b1);
                    }
        }
        __syncthreads();
    }

    #pragma unroll
    for (int mi = 0; mi < 2; mi++)
        #pragma unroll
        for (int ni = 0; ni < 4; ni++) {
            int r = m0 + wm + mi * 16 + gr;
            int c = n0 + wn + ni * 8 + gc * 2;
            float* cc = acc[mi][ni];
            if (MODE == 3) {
                __half* Ch = (__half*)Chv;
                __half* Cl = (__half*)Clv;
                int b = r >> 11, s = r & 2047;
                int h = c >> 6, d = c & 63;
                float b0 = bias[c], b1 = bias[c + 1];
                float v00 = cc[0] + b0, v01 = cc[1] + b1;
                float v10 = cc[2] + b0, v11 = cc[3] + b1;
                size_t base = ((size_t)(b * 16 + h) * 64 + d) * 2048;
                __half h00 = __float2half_rn(v00);
                __half h01 = __float2half_rn(v01);
                __half h10 = __float2half_rn(v10);
                __half h11 = __float2half_rn(v11);
                Ch[base + s]            = h00;
                Ch[base + 2048 + s]     = h01;
                Ch[base + s + 8]        = h10;
                Ch[base + 2048 + s + 8] = h11;
                Cl[base + s]            = __float2half_rn(v00 - __half2float(h00));
                Cl[base + 2048 + s]     = __float2half_rn(v01 - __half2float(h01));
                Cl[base + s + 8]        = __float2half_rn(v10 - __half2float(h10));
                Cl[base + 2048 + s + 8] = __float2half_rn(v11 - __half2float(h11));
            } else if (MODE == 5) {
                __nv_bfloat16* Ch = (__nv_bfloat16*)Chv;
                __nv_bfloat16* Cl = (__nv_bfloat16*)Clv;
                float b0 = bias[c], b1 = bias[c + 1];
                float v00 = cc[0] + b0, v01 = cc[1] + b1;
                float v10 = cc[2] + b0, v11 = cc[3] + b1;
                float h00 = __bfloat162float(__float2bfloat16_rn(v00));
                float h01 = __bfloat162float(__float2bfloat16_rn(v01));
                float h10 = __bfloat162float(__float2bfloat16_rn(v10));
                float h11 = __bfloat162float(__float2bfloat16_rn(v11));
                size_t o0 = (size_t)r * ldc + c;
                size_t o1 = (size_t)(r + 8) * ldc + c;
                *(unsigned*)&Ch[o0] = pack_bf2(v00, v01);
                *(unsigned*)&Ch[o1] = pack_bf2(v10, v11);
                *(unsigned*)&Cl[o0] = pack_bf2(v00 - h00, v01 - h01);
                *(unsigned*)&Cl[o1] = pack_bf2(v10 - h10, v11 - h11);
            } else {
                float b0 = 0.f, b1 = 0.f;
                if (bias) { b0 = bias[c]; b1 = bias[c + 1]; }
                float2 v0 = make_float2(cc[0] + b0, cc[1] + b1);
                float2 v1 = make_float2(cc[2] + b0, cc[3] + b1);
                *(float2*)&C[(size_t)r * ldc + c]       = v0;
                *(float2*)&C[(size_t)(r + 8) * ldc + c] = v1;
            }
        }
}

// ============================================================================
// Scores: P[z] = fp16((Q_h @ K_h^T)/8), pre-split bf16, K=64 single load.
// Block tile 128x128, 8 warps (4M x 2N), warp tile 32x64. ldmatrix fragments.
// ============================================================================
__global__ __launch_bounds__(256)
void scores_gemm(const __nv_bfloat16* __restrict__ Qh, const __nv_bfloat16* __restrict__ Ql,
                 const __nv_bfloat16* __restrict__ Kh, const __nv_bfloat16* __restrict__ Kl,
                 __half* __restrict__ P)
{
    constexpr int SA = 72;
    __shared__ __align__(16) __nv_bfloat16 AsH[128 * SA];
    __shared__ __align__(16) __nv_bfloat16 AsL[128 * SA];
    __shared__ __align__(16) __nv_bfloat16 BsH[128 * SA];
    __shared__ __align__(16) __nv_bfloat16 BsL[128 * SA];

    const int z = blockIdx.z, b = z >> 4, h = z & 15;
    const size_t qo = (size_t)b * SEQX * D_MODELX + h * D_HEADX;
    Qh += qo; Ql += qo; Kh += qo; Kl += qo;
    P += (size_t)z * SEQX * SEQX;

    const int tid  = threadIdx.x;
    const int m0   = blockIdx.y * 128;
    const int n0   = blockIdx.x * 128;
    const int warp = tid >> 5, lane = tid & 31;
    const int wm = (warp & 3) * 32;
    const int wn = (warp >> 2) * 64;
    const int gr = lane >> 2;
    const int gc = lane & 3;
    const int ti = lane >> 3, ri = lane & 7;

    #pragma unroll
    for (int i = 0; i < 4; i++) {
        int idx = tid + i * 256, row = idx >> 3, c8 = idx & 7;
        size_t oa = (size_t)(m0 + row) * D_MODELX + c8 * 8;
        size_t ob = (size_t)(n0 + row) * D_MODELX + c8 * 8;
        *(uint4*)&AsH[row * SA + c8 * 8] = *(const uint4*)(Qh + oa);
        *(uint4*)&AsL[row * SA + c8 * 8] = *(const uint4*)(Ql + oa);
        *(uint4*)&BsH[row * SA + c8 * 8] = *(const uint4*)(Kh + ob);
        *(uint4*)&BsL[row * SA + c8 * 8] = *(const uint4*)(Kl + ob);
    }
    __syncthreads();

    unsigned aHb[2], aLb[2], bHb[4], bLb[4];
    #pragma unroll
    for (int mi = 0; mi < 2; mi++) {
        int row = wm + mi * 16 + (ti & 1) * 8 + ri;
        int col = (ti >> 1) * 8;
        aHb[mi] = smem_u32(&AsH[row * SA + col]);
        aLb[mi] = smem_u32(&AsL[row * SA + col]);
    }
    #pragma unroll
    for (int nip = 0; nip < 4; nip++) {
        int row = wn + (nip * 2 + (ti >> 1)) * 8 + ri;
        int col = (ti & 1) * 8;
        bHb[nip] = smem_u32(&BsH[row * SA + col]);
        bLb[nip] = smem_u32(&BsL[row * SA + col]);
    }

    float acc[2][8][4] = {};

    #pragma unroll
    for (int ks = 0; ks < 4; ks++) {
        const int kb2 = ks * 32;
        unsigned aH[2][4], aL[2][4], bH[4][4], bL[4][4];
        #pragma unroll
        for (int mi = 0; mi < 2; mi++) {
            LDSM_X4(aH[mi][0], aH[mi][1], aH[mi][2], aH[mi][3], aHb[mi] + kb2);
            LDSM_X4(aL[mi][0], aL[mi][1], aL[mi][2], aL[mi][3], aLb[mi] + kb2);
        }
        #pragma unroll
        for (int nip = 0; nip < 4; nip++) {
            LDSM_X4(bH[nip][0], bH[nip][1], bH[nip][2], bH[nip][3], bHb[nip] + kb2);
            LDSM_X4(bL[nip][0], bL[nip][1], bL[nip][2], bL[nip][3], bLb[nip] + kb2);
        }
        #pragma unroll
        for (int nip = 0; nip < 4; nip++)
            #pragma unroll
            for (int hh = 0; hh < 2; hh++) {
                int ni = nip * 2 + hh;
                unsigned b0 = bH[nip][hh * 2], b1 = bH[nip][hh * 2 + 1];
                unsigned l0 = bL[nip][hh * 2], l1 = bL[nip][hh * 2 + 1];
                #pragma unroll
                for (int mi = 0; mi < 2; mi++) {
                    MMA_BF16(acc[mi][ni], aH[mi][0], aH[mi][1], aH[mi][2], aH[mi][3], b0, b1);
                    MMA_BF16(acc[mi][ni], aH[mi][0], aH[mi][1], aH[mi][2], aH[mi][3], l0, l1);
                    MMA_BF16(acc[mi][ni], aL[mi][0], aL[mi][1], aL[mi][2], aL[mi][3], b0, b1);
                }
            }
    }

    #pragma unroll
    for (int mi = 0; mi < 2; mi++)
        #pragma unroll
        for (int ni = 0; ni < 8; ni++) {
            int r = m0 + wm + mi * 16 + gr;
            int c = n0 + wn + ni * 8 + gc * 2;
            float* cc = acc[mi][ni];
            *(__half2*)&P[(size_t)r * SEQX + c] =
                __floats2half2_rn(cc[0] * 0.125f, cc[1] * 0.125f);
            *(__half2*)&P[(size_t)(r + 8) * SEQX + c] =
                __floats2half2_rn(cc[2] * 0.125f, cc[3] * 0.125f);
        }
}

// ============================================================================
// stats + head-average (no P rewrite)
// ============================================================================
__global__ __launch_bounds__(256)
void stats_avg_kernel(const __half* __restrict__ P, float* __restrict__ avg,
                      float* __restrict__ rmax, float* __restrict__ rinv)
{
    __shared__ float red[8];
    const int bq = blockIdx.x;
    const int t  = threadIdx.x;
    const int b  = bq >> 11;
    const int q  = bq & 2047;

    float avgacc[8] = {};

    for (int h = 0; h < NUM_HEADSX; ++h) {
        const int z = b * 16 + h;
        const __half2* p2 = (const __half2*)(P + ((size_t)z * SEQX + q) * SEQX);

        float2 v[4];
        float mx = -1e30f;
        #pragma unroll
        for (int i = 0; i < 4; i++) {
            v[i] = __half22float2(p2[t + i * 256]);
            mx = fmaxf(mx, fmaxf(v[i].x, v[i].y));
        }
        #pragma unroll
        for (int o = 16; o > 0; o >>= 1)
            mx = fmaxf(mx, __shfl_xor_sync(0xffffffffu, mx, o));
        if ((t & 31) == 0) red[t >> 5] = mx;
        __syncthreads();
        float bm = red[0];
        #pragma unroll
        for (int w = 1; w < 8; w++) bm = fmaxf(bm, red[w]);
        __syncthreads();

        float s = 0.f;
        #pragma unroll
        for (int i = 0; i < 4; i++) {
            v[i].x = __expf(v[i].x - bm);
            v[i].y = __expf(v[i].y - bm);
            s += v[i].x + v[i].y;
        }
        #pragma unroll
        for (int o = 16; o > 0; o >>= 1)
            s += __shfl_xor_sync(0xffffffffu, s, o);
        if ((t & 31) == 0) red[t >> 5] = s;
        __syncthreads();
        float bs = 0.f;
        #pragma unroll
        for (int w = 0; w < 8; w++) bs += red[w];
        float inv = 1.0f / bs;
        if (t == 0) {
            rmax[(size_t)z * SEQX + q] = bm;
            rinv[(size_t)z * SEQX + q] = inv;
        }

        #pragma unroll
        for (int i = 0; i < 4; i++) {
            avgacc[2 * i]     += v[i].x * inv;
            avgacc[2 * i + 1] += v[i].y * inv;
        }
        __syncthreads();
    }

    float2* a2 = (float2*)(avg + (size_t)bq * SEQX);
    #pragma unroll
    for (int i = 0; i < 4; i++)
        a2[t + i * 256] = make_float2(avgacc[2 * i] * (1.0f / NUM_HEADSX),
                                      avgacc[2 * i + 1] * (1.0f / NUM_HEADSX));
}

// ============================================================================
// AV: O_h = softmax(P)[z] @ Vt_h^T, exp on load, fp16 hi/lo V, ldmatrix frags.
// ============================================================================
__global__ __launch_bounds__(256)
void av_gemm(const __half* __restrict__ P,
             const __half* __restrict__ Vh, const __half* __restrict__ Vl,
             const float* __restrict__ rmax, const float* __restrict__ rinv,
             float* __restrict__ O)
{
    constexpr int BM = 128, BK = 64;
    constexpr int SA = 72;

    __shared__ __align__(16) __half As[BM * SA];
    __shared__ __align__(16) __half BsH[64 * SA];
    __shared__ __align__(16) __half BsL[64 * SA];
    __shared__ float sm_m[BM], sm_i[BM];

    const int z = blockIdx.z, b = z >> 4, h = z & 15;
    P  += (size_t)z * SEQX * SEQX;
    Vh += (size_t)z * D_HEADX * SEQX;
    Vl += (size_t)z * D_HEADX * SEQX;
    O  += (size_t)b * SEQX * D_MODELX + h * D_HEADX;
    rmax += (size_t)z * SEQX;
    rinv += (size_t)z * SEQX;

    const int tid  = threadIdx.x;
    const int m0   = blockIdx.y * BM;
    const int warp = tid >> 5, lane = tid & 31;
    const int wm = (warp & 3) * 32;
    const int wn = (warp >> 2) * 32;
    const int gr = lane >> 2;
    const int gc = lane & 3;
    const int ti = lane >> 3, ri = lane & 7;

    if (tid < BM) { sm_m[tid] = rmax[m0 + tid]; sm_i[tid] = rinv[m0 + tid]; }
    __syncthreads();

    unsigned ab[2], bHb[2], bLb[2];
    #pragma unroll
    for (int mi = 0; mi < 2; mi++) {
        int row = wm + mi * 16 + (ti & 1) * 8 + ri;
        int col = (ti >> 1) * 8;
        ab[mi] = smem_u32(&As[row * SA + col]);
    }
    #pragma unroll
    for (int nip = 0; nip < 2; nip++) {
        int row = wn + (nip * 2 + (ti >> 1)) * 8 + ri;
        int col = (ti & 1) * 8;
        bHb[nip] = smem_u32(&BsH[row * SA + col]);
        bLb[nip] = smem_u32(&BsL[row * SA + col]);
    }

    float acc[2][4][4] = {};
    uint4 pa[4], pbh[2], pbl[2];

    {
        #pragma unroll
        for (int i = 0; i < 4; i++) {
            int idx = tid + i * 256, row = idx >> 3, c8 = idx & 7;
            pa[i] = *(const uint4*)(P + (size_t)(m0 + row) * SEQX + c8 * 8);
        }
        #pragma unroll
        for (int i = 0; i < 2; i++) {
            int idx = tid + i * 256, row = idx >> 3, c8 = idx & 7;
            pbh[i] = *(const uint4*)(Vh + (size_t)row * SEQX + c8 * 8);
            pbl[i] = *(const uint4*)(Vl + (size_t)row * SEQX + c8 * 8);
        }
    }

    const int niter = SEQX / BK;  // 32
    for (int it = 0; it < niter; ++it) {
        #pragma unroll
        for (int i = 0; i < 4; i++) {
            int idx = tid + i * 256, row = idx >> 3, c8 = idx & 7;
            float m = sm_m[row], inv = sm_i[row];
            const __half2* hp = (const __half2*)&pa[i];
            uint4 out;
            unsigned* op = (unsigned*)&out;
            #pragma unroll
            for (int j = 0; j < 4; j++) {
                float2 f = __half22float2(hp[j]);
                __half2 e = __floats2half2_rn(__expf(f.x - m) * inv,
                                              __expf(f.y - m) * inv);
                op[j] = *(unsigned*)&e;
            }
            *(uint4*)&As[row * SA + c8 * 8] = out;
        }
        #pragma unroll
        for (int i = 0; i < 2; i++) {
            int idx = tid + i * 256, row = idx >> 3, c8 = idx & 7;
            *(uint4*)&BsH[row * SA + c8 * 8] = pbh[i];
            *(uint4*)&BsL[row * SA + c8 * 8] = pbl[i];
        }
        __syncthreads();

        if (it + 1 < niter) {
            int k0 = (it + 1) * BK;
            #pragma unroll
            for (int i = 0; i < 4; i++) {
                int idx = tid + i * 256, row = idx >> 3, c8 = idx & 7;
                pa[i] = *(const uint4*)(P + (size_t)(m0 + row) * SEQX + k0 + c8 * 8);
            }
            #pragma unroll
            for (int i = 0; i < 2; i++) {
                int idx = tid + i * 256, row = idx >> 3, c8 = idx & 7;
                pbh[i] = *(const uint4*)(Vh + (size_t)row * SEQX + k0 + c8 * 8);
                pbl[i] = *(const uint4*)(Vl + (size_t)row * SEQX + k0 + c8 * 8);
            }
        }

        #pragma unroll
        for (int ks = 0; ks < 4; ks++) {
            const int kb2 = ks * 32;
            unsigned a[2][4], bH[2][4], bL[2][4];
            #pragma unroll
            for (int mi = 0; mi < 2; mi++)
                LDSM_X4(a[mi][0], a[mi][1], a[mi][2], a[mi][3], ab[mi] + kb2);
            #pragma unroll
            for (int nip = 0; nip < 2; nip++) {
                LDSM_X4(bH[nip][0], bH[nip][1], bH[nip][2], bH[nip][3], bHb[nip] + kb2);
                LDSM_X4(bL[nip][0], bL[nip][1], bL[nip][2], bL[nip][3], bLb[nip] + kb2);
            }
            #pragma unroll
            for (int mi = 0; mi < 2; mi++)
                #pragma unroll
                for (int nip = 0; nip < 2; nip++)
                    #pragma unroll
                    for (int hh = 0; hh < 2; hh++) {
                        int ni = nip * 2 + hh;
                        MMA_F16(acc[mi][ni], a[mi][0], a[mi][1], a[mi][2], a[mi][3],
                                bH[nip][hh * 2], bH[nip][hh * 2 + 1]);
                        MMA_F16(acc[mi][ni], a[mi][0], a[mi][1], a[mi][2], a[mi][3],
                                bL[nip][hh * 2], bL[nip][hh * 2 + 1]);
                    }
        }
        __syncthreads();
    }

    #pragma unroll
    for (int mi = 0; mi < 2; mi++)
        #pragma unroll
        for (int ni = 0; ni < 4; ni++) {
            int r = m0 + wm + mi * 16 + gr;
            int c = wn + ni * 8 + gc * 2;
            float* cc = acc[mi][ni];
            *(float2*)&O[(size_t)r * D_MODELX + c]       = make_float2(cc[0], cc[1]);
            *(float2*)&O[(size_t)(r + 8) * D_MODELX + c] = make_float2(cc[2], cc[3]);
        }
}

// ============================================================================
// launch
// ============================================================================
extern "C" void kernel_launch(void* const* d_in, const int* in_sizes, int n_in,
                              void* d_out, int out_size)
{
    const float* x_q = (const float*)d_in[0];
    const float* x_k = (const float*)d_in[1];
    const float* x_v = (const float*)d_in[2];
    const float* Wq  = (const float*)d_in[3];
    const float* bq  = (const float*)d_in[4];
    const float* Wk  = (const float*)d_in[5];
    const float* bk  = (const float*)d_in[6];
    const float* Wv  = (const float*)d_in[7];
    const float* bv  = (const float*)d_in[8];
    const float* Wo  = (const float*)d_in[9];
    const float* bo  = (const float*)d_in[10];

    float* out = (float*)d_out;
    float* avg = out + (size_t)M_TOK * D_MODELX;

    __nv_bfloat16 *Qh, *Ql, *Kh, *Kl;
    __half *Vth, *Vtl, *P;
    float *gO, *rmax, *rinv;
    cudaGetSymbolAddress((void**)&Qh, g_Qh);
    cudaGetSymbolAddress((void**)&Ql, g_Ql);
    cudaGetSymbolAddress((void**)&Kh, g_Kh);
    cudaGetSymbolAddress((void**)&Kl, g_Kl);
    cudaGetSymbolAddress((void**)&Vth, g_Vth);
    cudaGetSymbolAddress((void**)&Vtl, g_Vtl);
    cudaGetSymbolAddress((void**)&gO, g_O);
    cudaGetSymbolAddress((void**)&P, g_P);
    cudaGetSymbolAddress((void**)&rmax, g_rmax);
    cudaGetSymbolAddress((void**)&rinv, g_rinv);

    dim3 blk(256);
    dim3 gproj(D_MODELX / 64, M_TOK / 128, 1);   // (16, 64)

    // 1-3) projections: Q/K -> bf16 hi/lo, V -> transposed fp16 hi/lo
    mma_gemm<5><<<gproj, blk>>>(x_q, Wq, nullptr, Qh, Ql,
                                D_MODELX, D_MODELX, D_MODELX, D_MODELX, bq);
    mma_gemm<5><<<gproj, blk>>>(x_k, Wk, nullptr, Kh, Kl,
                                D_MODELX, D_MODELX, D_MODELX, D_MODELX, bk);
    mma_gemm<3><<<gproj, blk>>>(x_v, Wv, nullptr, Vth, Vtl,
                                D_MODELX, D_MODELX, 0, D_MODELX, bv);

    // 4) scores: raw fp16 P = (Q_h @ K_h^T) / 8
    dim3 gsc(SEQX / 128, SEQX / 128, NZ);        // (16, 16, 64)
    scores_gemm<<<gsc, blk>>>(Qh, Ql, Kh, Kl, P);

    // 5) softmax stats + head-average (no P rewrite)
    stats_avg_kernel<<<M_TOK, blk>>>(P, avg, rmax, rinv);

    // 6) AV fp16 MMA with on-the-fly exp
    dim3 gav(1, SEQX / 128, NZ);                 // (1, 16, 64)
    av_gemm<<<gav, blk>>>(P, Vth, Vtl, rmax, rinv, gO);

    // 7) output projection (fp32 out)
    mma_gemm<0><<<gproj, blk>>>(gO, Wo, out, nullptr, nullptr,
                                D_MODELX, D_MODELX, D_MODELX, D_MODELX, bo);
}